// round 10
// baseline (speedup 1.0000x reference)
#include <cuda_runtime.h>
#include <math.h>
#include <stdint.h>

#define BB   8
#define C1   512
#define C2   256
#define SD   512
#define H0   64
#define H1   128
#define NPIX   (H1*H1)      // 16384
#define NPIX0  (H0*H0)      // 4096

typedef unsigned long long ull;

// packed f32x2 helpers (sm_100+ PTX)
__device__ __forceinline__ void ffma2(ull& acc, ull a, ull b) {
    asm("fma.rn.f32x2 %0, %1, %2, %0;" : "+l"(acc) : "l"(a), "l"(b));
}
__device__ __forceinline__ ull bcast2(float v) {
    ull p;
    asm("mov.b64 %0, {%1, %1};" : "=l"(p) : "r"(__float_as_uint(v)));
    return p;
}
__device__ __forceinline__ void unpack2(ull p, float& lo, float& hi) {
    unsigned int a, b;
    asm("mov.b64 {%0, %1}, %2;" : "=r"(a), "=r"(b) : "l"(p));
    lo = __uint_as_float(a); hi = __uint_as_float(b);
}

// ---------------- scratch (device globals; no allocation) ----------------
__device__ float g_s1[BB*C1];
__device__ float g_s2[BB*C2];
__device__ float g_s3[BB*C2];
__device__ float g_e1[BB*C2];
__device__ float g_e2[BB*C2];
__device__ float g_wsq1[C2*C1];
__device__ float g_wsq2[C2*C2];
__device__ float g_up [(size_t)BB*C1*NPIX];   // 268 MB
__device__ float g_h1 [(size_t)BB*C2*NPIX];   // 134 MB

// ---------------- styles: s = style @ (mod_w/sqrt(S)).T + mod_b ----------------
__global__ void k_styles(const float* __restrict__ w1, const float* __restrict__ w2,
                         const float* __restrict__ m1w, const float* __restrict__ m1b,
                         const float* __restrict__ m2w, const float* __restrict__ m2b,
                         const float* __restrict__ m3w, const float* __restrict__ m3b)
{
    int t = blockIdx.x*blockDim.x + threadIdx.x;
    const float inv = rsqrtf((float)SD);
    if (t < BB*C1) {
        int b = t / C1, i = t % C1;
        float a = 0.f;
        for (int k = 0; k < SD; k++) a += w1[b*SD+k] * m1w[i*SD+k];
        g_s1[t] = a*inv + m1b[i];
    } else if (t < BB*C1 + BB*C2) {
        int u = t - BB*C1; int b = u / C2, i = u % C2;
        float a = 0.f;
        for (int k = 0; k < SD; k++) a += w2[b*SD+k] * m2w[i*SD+k];
        g_s2[u] = a*inv + m2b[i];
    } else if (t < BB*C1 + 2*BB*C2) {
        int u = t - BB*C1 - BB*C2; int b = u / C2, i = u % C2;
        float a = 0.f;
        for (int k = 0; k < SD; k++) a += w2[b*SD+k] * m3w[i*SD+k];
        g_s3[u] = a*inv + m3b[i];
    }
}

// ---------------- per-(o,i) sum of squared 3x3 taps ----------------
__global__ void k_wsq(const float* __restrict__ w1c, const float* __restrict__ w2c)
{
    int t = blockIdx.x*blockDim.x + threadIdx.x;
    if (t < C2*C1) {
        float a = 0.f;
        #pragma unroll
        for (int k = 0; k < 9; k++) { float v = w1c[t*9+k]; a += v*v; }
        g_wsq1[t] = a;
    } else if (t < C2*C1 + C2*C2) {
        int u = t - C2*C1;
        float a = 0.f;
        #pragma unroll
        for (int k = 0; k < 9; k++) { float v = w2c[u*9+k]; a += v*v; }
        g_wsq2[u] = a;
    }
}

// ---------------- e[b,o] = scale * rsqrt(scale^2 * sum_i wsq[o,i]*s[b,i]^2 + eps) ----------------
__global__ void k_demod()
{
    int t = blockIdx.x*blockDim.x + threadIdx.x;
    const float sc1 = rsqrtf((float)(C1*9));
    const float sc2 = rsqrtf((float)(C2*9));
    if (t < BB*C2) {
        int b = t / C2, o = t % C2;
        float a = 0.f;
        for (int i = 0; i < C1; i++) { float s = g_s1[b*C1+i]; a += g_wsq1[o*C1+i]*s*s; }
        g_e1[t] = sc1 * rsqrtf(sc1*sc1*a + 1e-8f);
    } else if (t < 2*BB*C2) {
        int u = t - BB*C2; int b = u / C2, o = u % C2;
        float a = 0.f;
        for (int i = 0; i < C2; i++) { float s = g_s2[b*C2+i]; a += g_wsq2[o*C2+i]*s*s; }
        g_e2[u] = sc2 * rsqrtf(sc2*sc2*a + 1e-8f);
    }
}

// ---------------- bilinear 2x upsample (half-pixel, clamped) with s1 folded in ----------------
__global__ void k_upmod(const float* __restrict__ x)
{
    size_t t = (size_t)blockIdx.x*blockDim.x + threadIdx.x;
    if (t >= (size_t)BB*C1*NPIX) return;
    int p  = (int)(t % NPIX);
    int bc = (int)(t / NPIX);
    int X = p % H1, Y = p / H1;
    float sy = Y*0.5f - 0.25f, sx = X*0.5f - 0.25f;
    int y0 = (int)floorf(sy), x0 = (int)floorf(sx);
    float fy = sy - (float)y0, fx = sx - (float)x0;
    int y0c = max(y0, 0), y1c = min(y0+1, H0-1);
    int x0c = max(x0, 0), x1c = min(x0+1, H0-1);
    const float* xp = x + (size_t)bc*NPIX0;
    float v = (1.f-fy)*((1.f-fx)*xp[y0c*H0+x0c] + fx*xp[y0c*H0+x1c])
            +      fy *((1.f-fx)*xp[y1c*H0+x0c] + fx*xp[y1c*H0+x1c]);
    g_up[t] = v * g_s1[bc];
}

// ---------------- 3x3 conv, pad 1: 32 o-chans x (32x8) pixel tile per block ----------------
// 128 threads: po = tid/32 (4 o-subgroups of 8 chans), tx = tid%32 (x col, 8 y rows each)
// sIn stores PRE-PACKED {v,v} pairs (8B), so the inner loop's input fetch is a single
// aligned LDS.64 with no MOV packing; weight pairs also via LDS.64 from sW.
template<int CIN, bool MODIN>
__global__ __launch_bounds__(128, 4)
void k_conv3x3(const float* __restrict__ in, const float* __restrict__ wgt,
               const float* __restrict__ smod, const float* __restrict__ emod,
               const float* __restrict__ noise, const float* __restrict__ nw,
               float* __restrict__ out)
{
    const int KC = 8, TO = 32;
    __shared__ ull sIn[KC][10][34];                      // packed {v,v}, 21760 B
    __shared__ __align__(8) float sW [KC][9][TO+2];      // 9792 B

    int tid = threadIdx.x;
    int po  = tid >> 5;
    int tx  = tid & 31;
    int bz  = blockIdx.z;
    int b   = bz >> 3;
    int o0  = (bz & 7) * TO;
    int gx0 = blockIdx.x * 32;
    int gy0 = blockIdx.y * 8;

    // acc2[q][j]: packed pair over output chans (po*8 + 2q, +1), row j
    ull acc2[4][8];
    #pragma unroll
    for (int q = 0; q < 4; q++)
        #pragma unroll
        for (int j = 0; j < 8; j++) acc2[q][j] = 0ULL;

    for (int ci0 = 0; ci0 < CIN; ci0 += KC) {
        __syncthreads();
        // input tile 8 x 10 x 34 (halo, zero pad), packed {v,v}
        for (int idx = tid; idx < KC*10*34; idx += 128) {
            int c = idx / 340, rem = idx % 340;
            int r = rem / 34, col = rem % 34;
            int gy = gy0 + r - 1, gx = gx0 + col - 1;
            float v = 0.f;
            if (gy >= 0 && gy < H1 && gx >= 0 && gx < H1) {
                v = in[(size_t)(b*CIN + ci0 + c)*NPIX + gy*H1 + gx];
                if (MODIN) v *= smod[b*CIN + ci0 + c];
            }
            sIn[c][r][col] = bcast2(v);
        }
        // weights: per o, 72 consecutive floats (8 ci x 9 taps) -> coalesced
        for (int idx = tid; idx < TO*KC*9; idx += 128) {
            int o = idx / 72, rem = idx % 72;
            int c = rem / 9, tp = rem % 9;
            sW[c][tp][o] = wgt[(size_t)((o0 + o)*CIN + ci0 + c)*9 + tp];
        }
        __syncthreads();

        #pragma unroll
        for (int c = 0; c < KC; c++) {
            #pragma unroll
            for (int kx = 0; kx < 3; kx++) {
                ull vb[10];
                #pragma unroll
                for (int r = 0; r < 10; r++) vb[r] = sIn[c][r][tx + kx];   // LDS.64
                #pragma unroll
                for (int ky = 0; ky < 3; ky++) {
                    ull wp[4];
                    #pragma unroll
                    for (int q = 0; q < 4; q++)
                        wp[q] = *reinterpret_cast<const ull*>(&sW[c][ky*3+kx][po*8 + q*2]);
                    #pragma unroll
                    for (int q = 0; q < 4; q++)
                        #pragma unroll
                        for (int j = 0; j < 8; j++)
                            ffma2(acc2[q][j], wp[q], vb[ky + j]);
                }
            }
        }
    }

    float nwv = nw[0];
    #pragma unroll
    for (int j = 0; j < 8; j++) {
        int gy = gy0 + j, gx = gx0 + tx;
        float nz = nwv * noise[(size_t)b*NPIX + gy*H1 + gx];
        #pragma unroll
        for (int q = 0; q < 4; q++) {
            int o = o0 + po*8 + q*2;
            float a0, a1; unpack2(acc2[q][j], a0, a1);
            float e0 = emod[b*C2 + o], e1 = emod[b*C2 + o + 1];
            float v0 = a0*e0 + nz; v0 = (v0 > 0.f) ? v0 : 0.2f*v0;
            float v1 = a1*e1 + nz; v1 = (v1 > 0.f) ? v1 : 0.2f*v1;
            out[(size_t)(b*C2 + o    )*NPIX + gy*H1 + gx] = v0;
            out[(size_t)(b*C2 + o + 1)*NPIX + gy*H1 + gx] = v1;
        }
    }
}

// ---------------- to_rgb 1x1 (no demod) + upsampled skip ----------------
__global__ void k_rgb(const float* __restrict__ h, const float* __restrict__ rgbw,
                      const float* __restrict__ skip, float* __restrict__ outrgb)
{
    int b = blockIdx.y;
    __shared__ float sw[3][C2];
    for (int i = threadIdx.x; i < 3*C2; i += blockDim.x) {
        int c = i / C2, o = i % C2;
        sw[c][o] = rgbw[c*C2 + o] * g_s3[b*C2 + o] * 0.0625f;  // scale3 = 1/sqrt(256)
    }
    __syncthreads();
    int p = blockIdx.x*blockDim.x + threadIdx.x;  // exact cover: 64*256 = 16384
    float a0 = 0.f, a1 = 0.f, a2 = 0.f;
    for (int o = 0; o < C2; o++) {
        float v = h[(size_t)(b*C2 + o)*NPIX + p];
        a0 += sw[0][o]*v; a1 += sw[1][o]*v; a2 += sw[2][o]*v;
    }
    int X = p % H1, Y = p / H1;
    float sy = Y*0.5f - 0.25f, sx = X*0.5f - 0.25f;
    int y0 = (int)floorf(sy), x0 = (int)floorf(sx);
    float fy = sy - (float)y0, fx = sx - (float)x0;
    int y0c = max(y0, 0), y1c = min(y0+1, H0-1);
    int x0c = max(x0, 0), x1c = min(x0+1, H0-1);
    float a[3] = {a0, a1, a2};
    #pragma unroll
    for (int c = 0; c < 3; c++) {
        const float* sp = skip + (size_t)(b*3 + c)*NPIX0;
        float bv = (1.f-fy)*((1.f-fx)*sp[y0c*H0+x0c] + fx*sp[y0c*H0+x1c])
                 +      fy *((1.f-fx)*sp[y1c*H0+x0c] + fx*sp[y1c*H0+x1c]);
        outrgb[(size_t)(b*3 + c)*NPIX + p] = a[c] + bv;
    }
}

// ---------------- launch ----------------
extern "C" void kernel_launch(void* const* d_in, const int* in_sizes, int n_in,
                              void* d_out, int out_size)
{
    const float* x       = (const float*)d_in[0];
    const float* w1      = (const float*)d_in[1];
    const float* w2      = (const float*)d_in[2];
    const float* skip    = (const float*)d_in[3];
    const float* noise1  = (const float*)d_in[4];
    const float* noise2  = (const float*)d_in[5];
    const float* conv1_w = (const float*)d_in[6];
    const float* mod1_w  = (const float*)d_in[7];
    const float* mod1_b  = (const float*)d_in[8];
    const float* conv2_w = (const float*)d_in[9];
    const float* mod2_w  = (const float*)d_in[10];
    const float* mod2_b  = (const float*)d_in[11];
    const float* rgb_w   = (const float*)d_in[12];
    const float* mod3_w  = (const float*)d_in[13];
    const float* mod3_b  = (const float*)d_in[14];
    const float* nw1     = (const float*)d_in[15];
    const float* nw2     = (const float*)d_in[16];
    float* out = (float*)d_out;

    void *p_up, *p_h1, *p_e1, *p_e2, *p_s2;
    cudaGetSymbolAddress(&p_up, g_up);
    cudaGetSymbolAddress(&p_h1, g_h1);
    cudaGetSymbolAddress(&p_e1, g_e1);
    cudaGetSymbolAddress(&p_e2, g_e2);
    cudaGetSymbolAddress(&p_s2, g_s2);

    float* out_h   = out;                                // [8,256,128,128]
    float* out_rgb = out + (size_t)BB*C2*NPIX;           // [8,3,128,128]

    // 1. styles
    {
        int n = BB*C1 + 2*BB*C2;
        k_styles<<<(n + 255)/256, 256>>>(w1, w2, mod1_w, mod1_b, mod2_w, mod2_b, mod3_w, mod3_b);
    }
    // 2. weight square sums
    {
        int n = C2*C1 + C2*C2;
        k_wsq<<<(n + 255)/256, 256>>>(conv1_w, conv2_w);
    }
    // 3. demod scalars
    k_demod<<<(2*BB*C2 + 255)/256, 256>>>();
    // 4. upsample + modulate (s1)
    {
        size_t n = (size_t)BB*C1*NPIX;
        k_upmod<<<(unsigned)((n + 255)/256), 256>>>(x);
    }
    // 5. conv1 (input pre-modulated) -> g_h1, epilogue noise1 + lrelu
    k_conv3x3<C1, false><<<dim3(4, 16, BB*8), 128>>>(
        (const float*)p_up, conv1_w, nullptr, (const float*)p_e1, noise1, nw1, (float*)p_h1);
    // 6. conv2 (modulate by s2 at load) -> d_out h region, epilogue noise2 + lrelu
    k_conv3x3<C2, true ><<<dim3(4, 16, BB*8), 128>>>(
        (const float*)p_h1, conv2_w, (const float*)p_s2, (const float*)p_e2, noise2, nw2, out_h);
    // 7. to_rgb + upsampled skip -> d_out rgb region
    k_rgb<<<dim3(NPIX/256, BB), 256>>>(out_h, rgb_w, skip, out_rgb);
}

// round 11
// speedup vs baseline: 1.2833x; 1.2833x over previous
#include <cuda_runtime.h>
#include <math.h>
#include <stdint.h>

#define BB   8
#define C1   512
#define C2   256
#define SD   512
#define H0   64
#define H1   128
#define NPIX   (H1*H1)      // 16384
#define NPIX0  (H0*H0)      // 4096

typedef unsigned long long ull;

__device__ __forceinline__ void ffma2(ull& acc, ull a, ull b) {
    asm("fma.rn.f32x2 %0, %1, %2, %0;" : "+l"(acc) : "l"(a), "l"(b));
}
__device__ __forceinline__ ull bcast2(float v) {
    ull p;
    asm("mov.b64 %0, {%1, %1};" : "=l"(p) : "r"(__float_as_uint(v)));
    return p;
}
__device__ __forceinline__ void unpack2(ull p, float& lo, float& hi) {
    unsigned int a, b;
    asm("mov.b64 {%0, %1}, %2;" : "=r"(a), "=r"(b) : "l"(p));
    lo = __uint_as_float(a); hi = __uint_as_float(b);
}
__device__ __forceinline__ uint32_t smem_u32(const void* p) {
    uint32_t a;
    asm("{ .reg .u64 t; cvta.to.shared.u64 t, %1; cvt.u32.u64 %0, t; }" : "=r"(a) : "l"(p));
    return a;
}
__device__ __forceinline__ void cp4(uint32_t dst, const float* src, uint32_t sz) {
    asm volatile("cp.async.ca.shared.global [%0], [%1], 4, %2;" :: "r"(dst), "l"(src), "r"(sz));
}
__device__ __forceinline__ void cp16(uint32_t dst, const float* src) {
    asm volatile("cp.async.ca.shared.global [%0], [%1], 16;" :: "r"(dst), "l"(src));
}
#define CP_COMMIT() asm volatile("cp.async.commit_group;")

// ---------------- scratch (device globals; no allocation) ----------------
__device__ float g_s1[BB*C1];
__device__ float g_s2[BB*C2];
__device__ float g_s3[BB*C2];
__device__ float g_e1[BB*C2];
__device__ float g_e2[BB*C2];
__device__ float g_wsq1[C2*C1];
__device__ float g_wsq2[C2*C2];
__device__ float g_up [(size_t)BB*C1*NPIX];   // 268 MB
__device__ float g_h1 [(size_t)BB*C2*NPIX];   // 134 MB (stores h1 * s2)
__device__ float g_wt1[(size_t)C1*9*C2];      // transposed conv1 weights [ci][tap][o]
__device__ float g_wt2[(size_t)C2*9*C2];      // transposed conv2 weights

// ---------------- styles ----------------
__global__ void k_styles(const float* __restrict__ w1, const float* __restrict__ w2,
                         const float* __restrict__ m1w, const float* __restrict__ m1b,
                         const float* __restrict__ m2w, const float* __restrict__ m2b,
                         const float* __restrict__ m3w, const float* __restrict__ m3b)
{
    int t = blockIdx.x*blockDim.x + threadIdx.x;
    const float inv = rsqrtf((float)SD);
    if (t < BB*C1) {
        int b = t / C1, i = t % C1;
        float a = 0.f;
        for (int k = 0; k < SD; k++) a += w1[b*SD+k] * m1w[i*SD+k];
        g_s1[t] = a*inv + m1b[i];
    } else if (t < BB*C1 + BB*C2) {
        int u = t - BB*C1; int b = u / C2, i = u % C2;
        float a = 0.f;
        for (int k = 0; k < SD; k++) a += w2[b*SD+k] * m2w[i*SD+k];
        g_s2[u] = a*inv + m2b[i];
    } else if (t < BB*C1 + 2*BB*C2) {
        int u = t - BB*C1 - BB*C2; int b = u / C2, i = u % C2;
        float a = 0.f;
        for (int k = 0; k < SD; k++) a += w2[b*SD+k] * m3w[i*SD+k];
        g_s3[u] = a*inv + m3b[i];
    }
}

// ---------------- per-(o,i) sum of squared taps ----------------
__global__ void k_wsq(const float* __restrict__ w1c, const float* __restrict__ w2c)
{
    int t = blockIdx.x*blockDim.x + threadIdx.x;
    if (t < C2*C1) {
        float a = 0.f;
        #pragma unroll
        for (int k = 0; k < 9; k++) { float v = w1c[t*9+k]; a += v*v; }
        g_wsq1[t] = a;
    } else if (t < C2*C1 + C2*C2) {
        int u = t - C2*C1;
        float a = 0.f;
        #pragma unroll
        for (int k = 0; k < 9; k++) { float v = w2c[u*9+k]; a += v*v; }
        g_wsq2[u] = a;
    }
}

// ---------------- demod scalars ----------------
__global__ void k_demod()
{
    int t = blockIdx.x*blockDim.x + threadIdx.x;
    const float sc1 = rsqrtf((float)(C1*9));
    const float sc2 = rsqrtf((float)(C2*9));
    if (t < BB*C2) {
        int b = t / C2, o = t % C2;
        float a = 0.f;
        for (int i = 0; i < C1; i++) { float s = g_s1[b*C1+i]; a += g_wsq1[o*C1+i]*s*s; }
        g_e1[t] = sc1 * rsqrtf(sc1*sc1*a + 1e-8f);
    } else if (t < 2*BB*C2) {
        int u = t - BB*C2; int b = u / C2, o = u % C2;
        float a = 0.f;
        for (int i = 0; i < C2; i++) { float s = g_s2[b*C2+i]; a += g_wsq2[o*C2+i]*s*s; }
        g_e2[u] = sc2 * rsqrtf(sc2*sc2*a + 1e-8f);
    }
}

// ---------------- weight transpose: wt[ci][tap][o] = w[o][ci][tap] ----------------
__global__ void k_wtr(const float* __restrict__ w, float* __restrict__ wt, int CIN)
{
    int t = blockIdx.x*blockDim.x + threadIdx.x;
    if (t >= CIN*9*C2) return;
    int o = t % C2, tp = (t/C2) % 9, ci = t/(9*C2);
    wt[t] = w[((size_t)o*CIN + ci)*9 + tp];
}

// ---------------- bilinear 2x upsample * s1 ----------------
__global__ void k_upmod(const float* __restrict__ x)
{
    size_t t = (size_t)blockIdx.x*blockDim.x + threadIdx.x;
    if (t >= (size_t)BB*C1*NPIX) return;
    int p  = (int)(t % NPIX);
    int bc = (int)(t / NPIX);
    int X = p % H1, Y = p / H1;
    float sy = Y*0.5f - 0.25f, sx = X*0.5f - 0.25f;
    int y0 = (int)floorf(sy), x0 = (int)floorf(sx);
    float fy = sy - (float)y0, fx = sx - (float)x0;
    int y0c = max(y0, 0), y1c = min(y0+1, H0-1);
    int x0c = max(x0, 0), x1c = min(x0+1, H0-1);
    const float* xp = x + (size_t)bc*NPIX0;
    float v = (1.f-fy)*((1.f-fx)*xp[y0c*H0+x0c] + fx*xp[y0c*H0+x1c])
            +      fy *((1.f-fx)*xp[y1c*H0+x0c] + fx*xp[y1c*H0+x1c]);
    g_up[t] = v * g_s1[bc];
}

// ---------------- 3x3 conv, cp.async double-buffered, FFMA2 inner loop ----------------
// CTA: 32 o-chans x (32x8) pixels. 128 threads. Inputs RAW (modulation pre-folded).
// wt layout: [ci][tap][256 o] -> chunk slice rows are 128B contiguous (cp16).
// MULS2: epilogue extra multiply by smod2[b,o] (conv1 writing conv2's pre-modulated input).
template<int CIN, bool MULS2>
__global__ __launch_bounds__(128, 4)
void k_conv3x3(const float* __restrict__ in, const float* __restrict__ wt,
               const float* __restrict__ emod, const float* __restrict__ smod2,
               const float* __restrict__ noise, const float* __restrict__ nw,
               float* __restrict__ out)
{
    const int KC = 8, TO = 32;
    __shared__ float sIn[2][KC*10*34];            // 21760 B
    __shared__ __align__(16) float sW[2][KC*9*TO]; // 18432 B

    int tid = threadIdx.x;
    int po  = tid >> 5;
    int tx  = tid & 31;
    int bz  = blockIdx.z;
    int b   = bz >> 3;
    int o0  = (bz & 7) * TO;
    int gx0 = blockIdx.x * 32;
    int gy0 = blockIdx.y * 8;
    const int NCHUNK = CIN / KC;

    uint32_t sIn_a = smem_u32(&sIn[0][0]);
    uint32_t sW_a  = smem_u32(&sW[0][0]);

    const float* inB = in + (size_t)b*CIN*NPIX;

    // fill chunk k into buffer buf (cp.async only)
    auto fill = [&](int k, int buf) {
        int ci0 = k*KC;
        // input: KC x 10 x 34, zero-fill halo
        for (int idx = tid; idx < KC*10*34; idx += 128) {
            int c = idx / 340, rem = idx % 340;
            int r = rem / 34, col = rem % 34;
            int gy = gy0 + r - 1, gx = gx0 + col - 1;
            bool ok = ((unsigned)gy < H1) && ((unsigned)gx < H1);
            const float* src = inB + (size_t)(ci0 + c)*NPIX + (ok ? gy*H1 + gx : 0);
            cp4(sIn_a + (buf*(KC*10*34) + idx)*4, src, ok ? 4u : 0u);
        }
        // weights: KC*9 rows of 32 floats (128B) via 16B chunks
        for (int idx = tid; idx < KC*9*8; idx += 128) {
            int row = idx >> 3, v = idx & 7;       // row = c*9+tp
            const float* src = wt + ((size_t)ci0*9 + row)*C2 + o0 + v*4;
            cp16(sW_a + (buf*(KC*9*TO) + row*TO + v*4)*4, src);
        }
        CP_COMMIT();
    };

    ull acc2[4][8];
    #pragma unroll
    for (int q = 0; q < 4; q++)
        #pragma unroll
        for (int j = 0; j < 8; j++) acc2[q][j] = 0ULL;

    fill(0, 0);

    for (int k = 0; k < NCHUNK; k++) {
        int buf = k & 1;
        if (k + 1 < NCHUNK) {
            fill(k + 1, buf ^ 1);
            asm volatile("cp.async.wait_group 1;" ::: "memory");
        } else {
            asm volatile("cp.async.wait_group 0;" ::: "memory");
        }
        __syncthreads();

        const float* bI = &sIn[buf][0];
        const float* bW = &sW[buf][0];
        #pragma unroll
        for (int c = 0; c < KC; c++) {
            const float* pI = bI + c*340;
            const float* pW = bW + c*9*TO;
            #pragma unroll
            for (int kx = 0; kx < 3; kx++) {
                ull vb[10];
                #pragma unroll
                for (int r = 0; r < 10; r++) vb[r] = bcast2(pI[r*34 + tx + kx]);
                #pragma unroll
                for (int ky = 0; ky < 3; ky++) {
                    ull wp[4];
                    #pragma unroll
                    for (int q = 0; q < 4; q++)
                        wp[q] = *reinterpret_cast<const ull*>(&pW[(ky*3+kx)*TO + po*8 + q*2]);
                    #pragma unroll
                    for (int q = 0; q < 4; q++)
                        #pragma unroll
                        for (int j = 0; j < 8; j++)
                            ffma2(acc2[q][j], wp[q], vb[ky + j]);
                }
            }
        }
        __syncthreads();
    }

    float nwv = nw[0];
    #pragma unroll
    for (int j = 0; j < 8; j++) {
        int gy = gy0 + j, gx = gx0 + tx;
        float nz = nwv * noise[(size_t)b*NPIX + gy*H1 + gx];
        #pragma unroll
        for (int q = 0; q < 4; q++) {
            int o = o0 + po*8 + q*2;
            float a0, a1; unpack2(acc2[q][j], a0, a1);
            float e0 = emod[b*C2 + o], e1 = emod[b*C2 + o + 1];
            float v0 = a0*e0 + nz; v0 = (v0 > 0.f) ? v0 : 0.2f*v0;
            float v1 = a1*e1 + nz; v1 = (v1 > 0.f) ? v1 : 0.2f*v1;
            if (MULS2) {
                v0 *= smod2[b*C2 + o];
                v1 *= smod2[b*C2 + o + 1];
            }
            out[(size_t)(b*C2 + o    )*NPIX + gy*H1 + gx] = v0;
            out[(size_t)(b*C2 + o + 1)*NPIX + gy*H1 + gx] = v1;
        }
    }
}

// ---------------- to_rgb 1x1 (no demod) + upsampled skip ----------------
// NOTE: h input here is the UNmodulated conv2 output (d_out h region).
__global__ void k_rgb(const float* __restrict__ h, const float* __restrict__ rgbw,
                      const float* __restrict__ skip, float* __restrict__ outrgb)
{
    int b = blockIdx.y;
    __shared__ float sw[3][C2];
    for (int i = threadIdx.x; i < 3*C2; i += blockDim.x) {
        int c = i / C2, o = i % C2;
        sw[c][o] = rgbw[c*C2 + o] * g_s3[b*C2 + o] * 0.0625f;  // 1/sqrt(256)
    }
    __syncthreads();
    int p = blockIdx.x*blockDim.x + threadIdx.x;
    float a0 = 0.f, a1 = 0.f, a2 = 0.f;
    for (int o = 0; o < C2; o++) {
        float v = h[(size_t)(b*C2 + o)*NPIX + p];
        a0 += sw[0][o]*v; a1 += sw[1][o]*v; a2 += sw[2][o]*v;
    }
    int X = p % H1, Y = p / H1;
    float sy = Y*0.5f - 0.25f, sx = X*0.5f - 0.25f;
    int y0 = (int)floorf(sy), x0 = (int)floorf(sx);
    float fy = sy - (float)y0, fx = sx - (float)x0;
    int y0c = max(y0, 0), y1c = min(y0+1, H0-1);
    int x0c = max(x0, 0), x1c = min(x0+1, H0-1);
    float a[3] = {a0, a1, a2};
    #pragma unroll
    for (int c = 0; c < 3; c++) {
        const float* sp = skip + (size_t)(b*3 + c)*NPIX0;
        float bv = (1.f-fy)*((1.f-fx)*sp[y0c*H0+x0c] + fx*sp[y0c*H0+x1c])
                 +      fy *((1.f-fx)*sp[y1c*H0+x0c] + fx*sp[y1c*H0+x1c]);
        outrgb[(size_t)(b*3 + c)*NPIX + p] = a[c] + bv;
    }
}

// ---------------- launch ----------------
extern "C" void kernel_launch(void* const* d_in, const int* in_sizes, int n_in,
                              void* d_out, int out_size)
{
    const float* x       = (const float*)d_in[0];
    const float* w1      = (const float*)d_in[1];
    const float* w2      = (const float*)d_in[2];
    const float* skip    = (const float*)d_in[3];
    const float* noise1  = (const float*)d_in[4];
    const float* noise2  = (const float*)d_in[5];
    const float* conv1_w = (const float*)d_in[6];
    const float* mod1_w  = (const float*)d_in[7];
    const float* mod1_b  = (const float*)d_in[8];
    const float* conv2_w = (const float*)d_in[9];
    const float* mod2_w  = (const float*)d_in[10];
    const float* mod2_b  = (const float*)d_in[11];
    const float* rgb_w   = (const float*)d_in[12];
    const float* mod3_w  = (const float*)d_in[13];
    const float* mod3_b  = (const float*)d_in[14];
    const float* nw1     = (const float*)d_in[15];
    const float* nw2     = (const float*)d_in[16];
    float* out = (float*)d_out;

    void *p_up, *p_h1, *p_e1, *p_e2, *p_s2, *p_wt1, *p_wt2;
    cudaGetSymbolAddress(&p_up, g_up);
    cudaGetSymbolAddress(&p_h1, g_h1);
    cudaGetSymbolAddress(&p_e1, g_e1);
    cudaGetSymbolAddress(&p_e2, g_e2);
    cudaGetSymbolAddress(&p_s2, g_s2);
    cudaGetSymbolAddress(&p_wt1, g_wt1);
    cudaGetSymbolAddress(&p_wt2, g_wt2);

    float* out_h   = out;                                // [8,256,128,128]
    float* out_rgb = out + (size_t)BB*C2*NPIX;           // [8,3,128,128]

    // 1. styles
    {
        int n = BB*C1 + 2*BB*C2;
        k_styles<<<(n + 255)/256, 256>>>(w1, w2, mod1_w, mod1_b, mod2_w, mod2_b, mod3_w, mod3_b);
    }
    // 2. weight square sums + demod scalars
    {
        int n = C2*C1 + C2*C2;
        k_wsq<<<(n + 255)/256, 256>>>(conv1_w, conv2_w);
    }
    k_demod<<<(2*BB*C2 + 255)/256, 256>>>();
    // 3. weight transposes
    k_wtr<<<(C1*9*C2 + 255)/256, 256>>>(conv1_w, (float*)p_wt1, C1);
    k_wtr<<<(C2*9*C2 + 255)/256, 256>>>(conv2_w, (float*)p_wt2, C2);
    // 4. upsample + modulate (s1)
    {
        size_t n = (size_t)BB*C1*NPIX;
        k_upmod<<<(unsigned)((n + 255)/256), 256>>>(x);
    }
    // 5. conv1 -> g_h1 (epilogue: e1, noise1, lrelu, then * s2 for conv2's input)
    k_conv3x3<C1, true ><<<dim3(4, 16, BB*8), 128>>>(
        (const float*)p_up, (const float*)p_wt1,
        (const float*)p_e1, (const float*)p_s2, noise1, nw1, (float*)p_h1);
    // 6. conv2 (raw input) -> d_out h region
    k_conv3x3<C2, false><<<dim3(4, 16, BB*8), 128>>>(
        (const float*)p_h1, (const float*)p_wt2,
        (const float*)p_e2, nullptr, noise2, nw2, out_h);
    // 7. to_rgb + upsampled skip
    k_rgb<<<dim3(NPIX/256, BB), 256>>>(out_h, rgb_w, skip, out_rgb);
}

// round 12
// speedup vs baseline: 1.2950x; 1.0091x over previous
#include <cuda_runtime.h>
#include <math.h>
#include <stdint.h>

#define BB   8
#define C1   512
#define C2   256
#define SD   512
#define H0   64
#define H1   128
#define NPIX   (H1*H1)      // 16384
#define NPIX0  (H0*H0)      // 4096

typedef unsigned long long ull;

__device__ __forceinline__ void ffma2(ull& acc, ull a, ull b) {
    asm("fma.rn.f32x2 %0, %1, %2, %0;" : "+l"(acc) : "l"(a), "l"(b));
}
__device__ __forceinline__ ull bcast2(float v) {
    ull p;
    asm("mov.b64 %0, {%1, %1};" : "=l"(p) : "r"(__float_as_uint(v)));
    return p;
}
__device__ __forceinline__ void unpack2(ull p, float& lo, float& hi) {
    unsigned int a, b;
    asm("mov.b64 {%0, %1}, %2;" : "=r"(a), "=r"(b) : "l"(p));
    lo = __uint_as_float(a); hi = __uint_as_float(b);
}
__device__ __forceinline__ uint32_t smem_u32(const void* p) {
    uint32_t a;
    asm("{ .reg .u64 t; cvta.to.shared.u64 t, %1; cvt.u32.u64 %0, t; }" : "=r"(a) : "l"(p));
    return a;
}
__device__ __forceinline__ void cp4(uint32_t dst, const float* src, uint32_t sz) {
    asm volatile("cp.async.ca.shared.global [%0], [%1], 4, %2;" :: "r"(dst), "l"(src), "r"(sz));
}
__device__ __forceinline__ void cp16(uint32_t dst, const float* src) {
    asm volatile("cp.async.ca.shared.global [%0], [%1], 16;" :: "r"(dst), "l"(src));
}
#define CP_COMMIT() asm volatile("cp.async.commit_group;")

// ---------------- scratch (device globals; no allocation) ----------------
__device__ float g_s1[BB*C1];
__device__ float g_s2[BB*C2];
__device__ float g_s3[BB*C2];
__device__ float g_e1[BB*C2];
__device__ float g_e2[BB*C2];
__device__ float g_wsq1[C2*C1];
__device__ float g_wsq2[C2*C2];
__device__ float g_up [(size_t)BB*C1*NPIX];   // 268 MB
__device__ float g_h1 [(size_t)BB*C2*NPIX];   // 134 MB (stores h1 * s2)
__device__ float g_wt1[(size_t)C1*9*C2];      // transposed conv1 weights [ci][tap][o]
__device__ float g_wt2[(size_t)C2*9*C2];      // transposed conv2 weights

// ---------------- styles ----------------
__global__ void k_styles(const float* __restrict__ w1, const float* __restrict__ w2,
                         const float* __restrict__ m1w, const float* __restrict__ m1b,
                         const float* __restrict__ m2w, const float* __restrict__ m2b,
                         const float* __restrict__ m3w, const float* __restrict__ m3b)
{
    int t = blockIdx.x*blockDim.x + threadIdx.x;
    const float inv = rsqrtf((float)SD);
    if (t < BB*C1) {
        int b = t / C1, i = t % C1;
        float a = 0.f;
        for (int k = 0; k < SD; k++) a += w1[b*SD+k] * m1w[i*SD+k];
        g_s1[t] = a*inv + m1b[i];
    } else if (t < BB*C1 + BB*C2) {
        int u = t - BB*C1; int b = u / C2, i = u % C2;
        float a = 0.f;
        for (int k = 0; k < SD; k++) a += w2[b*SD+k] * m2w[i*SD+k];
        g_s2[u] = a*inv + m2b[i];
    } else if (t < BB*C1 + 2*BB*C2) {
        int u = t - BB*C1 - BB*C2; int b = u / C2, i = u % C2;
        float a = 0.f;
        for (int k = 0; k < SD; k++) a += w2[b*SD+k] * m3w[i*SD+k];
        g_s3[u] = a*inv + m3b[i];
    }
}

// ---------------- per-(o,i) sum of squared taps ----------------
__global__ void k_wsq(const float* __restrict__ w1c, const float* __restrict__ w2c)
{
    int t = blockIdx.x*blockDim.x + threadIdx.x;
    if (t < C2*C1) {
        float a = 0.f;
        #pragma unroll
        for (int k = 0; k < 9; k++) { float v = w1c[t*9+k]; a += v*v; }
        g_wsq1[t] = a;
    } else if (t < C2*C1 + C2*C2) {
        int u = t - C2*C1;
        float a = 0.f;
        #pragma unroll
        for (int k = 0; k < 9; k++) { float v = w2c[u*9+k]; a += v*v; }
        g_wsq2[u] = a;
    }
}

// ---------------- demod scalars ----------------
__global__ void k_demod()
{
    int t = blockIdx.x*blockDim.x + threadIdx.x;
    const float sc1 = rsqrtf((float)(C1*9));
    const float sc2 = rsqrtf((float)(C2*9));
    if (t < BB*C2) {
        int b = t / C2, o = t % C2;
        float a = 0.f;
        for (int i = 0; i < C1; i++) { float s = g_s1[b*C1+i]; a += g_wsq1[o*C1+i]*s*s; }
        g_e1[t] = sc1 * rsqrtf(sc1*sc1*a + 1e-8f);
    } else if (t < 2*BB*C2) {
        int u = t - BB*C2; int b = u / C2, o = u % C2;
        float a = 0.f;
        for (int i = 0; i < C2; i++) { float s = g_s2[b*C2+i]; a += g_wsq2[o*C2+i]*s*s; }
        g_e2[u] = sc2 * rsqrtf(sc2*sc2*a + 1e-8f);
    }
}

// ---------------- weight transpose: wt[ci][tap][o] = w[o][ci][tap] ----------------
__global__ void k_wtr(const float* __restrict__ w, float* __restrict__ wt, int CIN)
{
    int t = blockIdx.x*blockDim.x + threadIdx.x;
    if (t >= CIN*9*C2) return;
    int o = t % C2, tp = (t/C2) % 9, ci = t/(9*C2);
    wt[t] = w[((size_t)o*CIN + ci)*9 + tp];
}

// ---------------- bilinear 2x upsample * s1 (2 X-pixels per thread, float2 store) ----------------
__global__ void k_upmod(const float* __restrict__ x)
{
    size_t t = (size_t)blockIdx.x*blockDim.x + threadIdx.x;
    if (t >= (size_t)BB*C1*NPIX/2) return;
    int ph = (int)(t % (NPIX/2));          // pixel-pair index
    int bc = (int)(t / (NPIX/2));
    int Y = ph >> 6;                        // / (H1/2)
    int tX = ph & 63;                       // pair: X = 2t, 2t+1
    float sy = Y*0.5f - 0.25f;
    int y0 = (int)floorf(sy); float fy = sy - (float)y0;
    int y0c = max(y0, 0), y1c = min(y0+1, H0-1);
    const float* xp = x + (size_t)bc*NPIX0;
    const float* r0 = xp + y0c*H0;
    const float* r1 = xp + y1c*H0;
    float s = g_s1[bc];
    // X=2t: x0=t-1, fx=0.75 ; X=2t+1: x0=t, fx=0.25   (clamped)
    int xm = max(tX-1, 0), xc = tX, xpn = min(tX+1, H0-1);
    float a0 = r0[xm], a1 = r0[xc], a2 = r0[xpn];
    float b0 = r1[xm], b1 = r1[xc], b2 = r1[xpn];
    float top0 = 0.25f*a0 + 0.75f*a1;      // X=2t, row y0
    float bot0 = 0.25f*b0 + 0.75f*b1;
    float top1 = 0.75f*a1 + 0.25f*a2;      // X=2t+1, row y0
    float bot1 = 0.75f*b1 + 0.25f*b2;
    float v0 = ((1.f-fy)*top0 + fy*bot0) * s;
    float v1 = ((1.f-fy)*top1 + fy*bot1) * s;
    *reinterpret_cast<float2*>(&g_up[(size_t)bc*NPIX + Y*H1 + tX*2]) = make_float2(v0, v1);
}

// ---------------- 3x3 conv, cp.async double-buffered, ONE barrier per chunk ----------------
// CTA: 32 o-chans x (32x8) pixels. 128 threads. Inputs RAW (modulation pre-folded).
// wt layout: [ci][tap][256 o]. MULS2: epilogue multiplies by smod2 (conv1 -> conv2 input).
// Loop order per chunk k: wait_group 0 (fill(k) done, issued one chunk ago) -> sync ->
// issue fill(k+1) -> compute(k). At the sync all warps finished compute(k-1), so
// fill(k+1) overwriting buffer (k+1)&1 == (k-1)&1 is safe. One barrier, same overlap.
template<int CIN, bool MULS2>
__global__ __launch_bounds__(128, 4)
void k_conv3x3(const float* __restrict__ in, const float* __restrict__ wt,
               const float* __restrict__ emod, const float* __restrict__ smod2,
               const float* __restrict__ noise, const float* __restrict__ nw,
               float* __restrict__ out)
{
    const int KC = 8, TO = 32;
    __shared__ float sIn[2][KC*10*34];             // 21760 B
    __shared__ __align__(16) float sW[2][KC*9*TO]; // 18432 B

    int tid = threadIdx.x;
    int po  = tid >> 5;
    int tx  = tid & 31;
    int bz  = blockIdx.z;
    int b   = bz >> 3;
    int o0  = (bz & 7) * TO;
    int gx0 = blockIdx.x * 32;
    int gy0 = blockIdx.y * 8;
    const int NCHUNK = CIN / KC;

    uint32_t sIn_a = smem_u32(&sIn[0][0]);
    uint32_t sW_a  = smem_u32(&sW[0][0]);

    const float* inB = in + (size_t)b*CIN*NPIX;

    auto fill = [&](int k, int buf) {
        int ci0 = k*KC;
        for (int idx = tid; idx < KC*10*34; idx += 128) {
            int c = idx / 340, rem = idx % 340;
            int r = rem / 34, col = rem % 34;
            int gy = gy0 + r - 1, gx = gx0 + col - 1;
            bool ok = ((unsigned)gy < H1) && ((unsigned)gx < H1);
            const float* src = inB + (size_t)(ci0 + c)*NPIX + (ok ? gy*H1 + gx : 0);
            cp4(sIn_a + (buf*(KC*10*34) + idx)*4, src, ok ? 4u : 0u);
        }
        for (int idx = tid; idx < KC*9*8; idx += 128) {
            int row = idx >> 3, v = idx & 7;
            const float* src = wt + ((size_t)ci0*9 + row)*C2 + o0 + v*4;
            cp16(sW_a + (buf*(KC*9*TO) + row*TO + v*4)*4, src);
        }
        CP_COMMIT();
    };

    ull acc2[4][8];
    #pragma unroll
    for (int q = 0; q < 4; q++)
        #pragma unroll
        for (int j = 0; j < 8; j++) acc2[q][j] = 0ULL;

    fill(0, 0);

    for (int k = 0; k < NCHUNK; k++) {
        int buf = k & 1;
        asm volatile("cp.async.wait_group 0;" ::: "memory");
        __syncthreads();
        if (k + 1 < NCHUNK) fill(k + 1, buf ^ 1);

        const float* bI = &sIn[buf][0];
        const float* bW = &sW[buf][0];
        #pragma unroll
        for (int c = 0; c < KC; c++) {
            const float* pI = bI + c*340;
            const float* pW = bW + c*9*TO;
            #pragma unroll
            for (int kx = 0; kx < 3; kx++) {
                ull vb[10];
                #pragma unroll
                for (int r = 0; r < 10; r++) vb[r] = bcast2(pI[r*34 + tx + kx]);
                #pragma unroll
                for (int ky = 0; ky < 3; ky++) {
                    ull wp[4];
                    #pragma unroll
                    for (int q = 0; q < 4; q++)
                        wp[q] = *reinterpret_cast<const ull*>(&pW[(ky*3+kx)*TO + po*8 + q*2]);
                    #pragma unroll
                    for (int q = 0; q < 4; q++)
                        #pragma unroll
                        for (int j = 0; j < 8; j++)
                            ffma2(acc2[q][j], wp[q], vb[ky + j]);
                }
            }
        }
    }

    float nwv = nw[0];
    #pragma unroll
    for (int j = 0; j < 8; j++) {
        int gy = gy0 + j, gx = gx0 + tx;
        float nz = nwv * noise[(size_t)b*NPIX + gy*H1 + gx];
        #pragma unroll
        for (int q = 0; q < 4; q++) {
            int o = o0 + po*8 + q*2;
            float a0, a1; unpack2(acc2[q][j], a0, a1);
            float e0 = emod[b*C2 + o], e1 = emod[b*C2 + o + 1];
            float v0 = a0*e0 + nz; v0 = (v0 > 0.f) ? v0 : 0.2f*v0;
            float v1 = a1*e1 + nz; v1 = (v1 > 0.f) ? v1 : 0.2f*v1;
            if (MULS2) {
                v0 *= smod2[b*C2 + o];
                v1 *= smod2[b*C2 + o + 1];
            }
            out[(size_t)(b*C2 + o    )*NPIX + gy*H1 + gx] = v0;
            out[(size_t)(b*C2 + o + 1)*NPIX + gy*H1 + gx] = v1;
        }
    }
}

// ---------------- to_rgb 1x1 (no demod) + upsampled skip ----------------
__global__ void k_rgb(const float* __restrict__ h, const float* __restrict__ rgbw,
                      const float* __restrict__ skip, float* __restrict__ outrgb)
{
    int b = blockIdx.y;
    __shared__ float sw[3][C2];
    for (int i = threadIdx.x; i < 3*C2; i += blockDim.x) {
        int c = i / C2, o = i % C2;
        sw[c][o] = rgbw[c*C2 + o] * g_s3[b*C2 + o] * 0.0625f;  // 1/sqrt(256)
    }
    __syncthreads();
    int p = blockIdx.x*blockDim.x + threadIdx.x;
    float a0 = 0.f, a1 = 0.f, a2 = 0.f;
    for (int o = 0; o < C2; o++) {
        float v = h[(size_t)(b*C2 + o)*NPIX + p];
        a0 += sw[0][o]*v; a1 += sw[1][o]*v; a2 += sw[2][o]*v;
    }
    int X = p % H1, Y = p / H1;
    float sy = Y*0.5f - 0.25f, sx = X*0.5f - 0.25f;
    int y0 = (int)floorf(sy), x0 = (int)floorf(sx);
    float fy = sy - (float)y0, fx = sx - (float)x0;
    int y0c = max(y0, 0), y1c = min(y0+1, H0-1);
    int x0c = max(x0, 0), x1c = min(x0+1, H0-1);
    float a[3] = {a0, a1, a2};
    #pragma unroll
    for (int c = 0; c < 3; c++) {
        const float* sp = skip + (size_t)(b*3 + c)*NPIX0;
        float bv = (1.f-fy)*((1.f-fx)*sp[y0c*H0+x0c] + fx*sp[y0c*H0+x1c])
                 +      fy *((1.f-fx)*sp[y1c*H0+x0c] + fx*sp[y1c*H0+x1c]);
        outrgb[(size_t)(b*3 + c)*NPIX + p] = a[c] + bv;
    }
}

// ---------------- launch ----------------
extern "C" void kernel_launch(void* const* d_in, const int* in_sizes, int n_in,
                              void* d_out, int out_size)
{
    const float* x       = (const float*)d_in[0];
    const float* w1      = (const float*)d_in[1];
    const float* w2      = (const float*)d_in[2];
    const float* skip    = (const float*)d_in[3];
    const float* noise1  = (const float*)d_in[4];
    const float* noise2  = (const float*)d_in[5];
    const float* conv1_w = (const float*)d_in[6];
    const float* mod1_w  = (const float*)d_in[7];
    const float* mod1_b  = (const float*)d_in[8];
    const float* conv2_w = (const float*)d_in[9];
    const float* mod2_w  = (const float*)d_in[10];
    const float* mod2_b  = (const float*)d_in[11];
    const float* rgb_w   = (const float*)d_in[12];
    const float* mod3_w  = (const float*)d_in[13];
    const float* mod3_b  = (const float*)d_in[14];
    const float* nw1     = (const float*)d_in[15];
    const float* nw2     = (const float*)d_in[16];
    float* out = (float*)d_out;

    void *p_up, *p_h1, *p_e1, *p_e2, *p_s2, *p_wt1, *p_wt2;
    cudaGetSymbolAddress(&p_up, g_up);
    cudaGetSymbolAddress(&p_h1, g_h1);
    cudaGetSymbolAddress(&p_e1, g_e1);
    cudaGetSymbolAddress(&p_e2, g_e2);
    cudaGetSymbolAddress(&p_s2, g_s2);
    cudaGetSymbolAddress(&p_wt1, g_wt1);
    cudaGetSymbolAddress(&p_wt2, g_wt2);

    float* out_h   = out;                                // [8,256,128,128]
    float* out_rgb = out + (size_t)BB*C2*NPIX;           // [8,3,128,128]

    // 1. styles
    {
        int n = BB*C1 + 2*BB*C2;
        k_styles<<<(n + 255)/256, 256>>>(w1, w2, mod1_w, mod1_b, mod2_w, mod2_b, mod3_w, mod3_b);
    }
    // 2. weight square sums + demod scalars
    {
        int n = C2*C1 + C2*C2;
        k_wsq<<<(n + 255)/256, 256>>>(conv1_w, conv2_w);
    }
    k_demod<<<(2*BB*C2 + 255)/256, 256>>>();
    // 3. weight transposes
    k_wtr<<<(C1*9*C2 + 255)/256, 256>>>(conv1_w, (float*)p_wt1, C1);
    k_wtr<<<(C2*9*C2 + 255)/256, 256>>>(conv2_w, (float*)p_wt2, C2);
    // 4. upsample + modulate (s1), 2 px/thread
    {
        size_t n = (size_t)BB*C1*NPIX/2;
        k_upmod<<<(unsigned)((n + 255)/256), 256>>>(x);
    }
    // 5. conv1 -> g_h1 (epilogue: e1, noise1, lrelu, then * s2 for conv2's input)
    k_conv3x3<C1, true ><<<dim3(4, 16, BB*8), 128>>>(
        (const float*)p_up, (const float*)p_wt1,
        (const float*)p_e1, (const float*)p_s2, noise1, nw1, (float*)p_h1);
    // 6. conv2 (raw input) -> d_out h region
    k_conv3x3<C2, false><<<dim3(4, 16, BB*8), 128>>>(
        (const float*)p_h1, (const float*)p_wt2,
        (const float*)p_e2, nullptr, noise2, nw2, out_h);
    // 7. to_rgb + upsampled skip
    k_rgb<<<dim3(NPIX/256, BB), 256>>>(out_h, rgb_w, skip, out_rgb);
}

// round 13
// speedup vs baseline: 1.3262x; 1.0241x over previous
#include <cuda_runtime.h>
#include <math.h>
#include <stdint.h>

#define BB   8
#define C1   512
#define C2   256
#define SD   512
#define H0   64
#define H1   128
#define NPIX   (H1*H1)      // 16384
#define NPIX0  (H0*H0)      // 4096

typedef unsigned long long ull;

__device__ __forceinline__ void ffma2(ull& acc, ull a, ull b) {
    asm("fma.rn.f32x2 %0, %1, %2, %0;" : "+l"(acc) : "l"(a), "l"(b));
}
__device__ __forceinline__ ull bcast2(float v) {
    ull p;
    asm("mov.b64 %0, {%1, %1};" : "=l"(p) : "r"(__float_as_uint(v)));
    return p;
}
__device__ __forceinline__ void unpack2(ull p, float& lo, float& hi) {
    unsigned int a, b;
    asm("mov.b64 {%0, %1}, %2;" : "=r"(a), "=r"(b) : "l"(p));
    lo = __uint_as_float(a); hi = __uint_as_float(b);
}
__device__ __forceinline__ uint32_t smem_u32(const void* p) {
    uint32_t a;
    asm("{ .reg .u64 t; cvta.to.shared.u64 t, %1; cvt.u32.u64 %0, t; }" : "=r"(a) : "l"(p));
    return a;
}
__device__ __forceinline__ void cp4(uint32_t dst, const float* src, uint32_t sz) {
    asm volatile("cp.async.ca.shared.global [%0], [%1], 4, %2;" :: "r"(dst), "l"(src), "r"(sz));
}
__device__ __forceinline__ void cp16(uint32_t dst, const float* src) {
    asm volatile("cp.async.ca.shared.global [%0], [%1], 16;" :: "r"(dst), "l"(src));
}
__device__ __forceinline__ void cp16z(uint32_t dst, const float* src, uint32_t sz) {
    asm volatile("cp.async.ca.shared.global [%0], [%1], 16, %2;" :: "r"(dst), "l"(src), "r"(sz));
}
#define CP_COMMIT() asm volatile("cp.async.commit_group;")

// ---------------- scratch (device globals; no allocation) ----------------
__device__ float g_s1[BB*C1];
__device__ float g_s2[BB*C2];
__device__ float g_s3[BB*C2];
__device__ float g_e1[BB*C2];
__device__ float g_e2[BB*C2];
__device__ float g_wsq1[C2*C1];
__device__ float g_wsq2[C2*C2];
__device__ float g_up [(size_t)BB*C1*NPIX];   // 268 MB
__device__ float g_h1 [(size_t)BB*C2*NPIX];   // 134 MB (stores h1 * s2)
__device__ float g_wt1[(size_t)C1*9*C2];      // transposed conv1 weights [ci][tap][o]
__device__ float g_wt2[(size_t)C2*9*C2];      // transposed conv2 weights

// ---------------- styles ----------------
__global__ void k_styles(const float* __restrict__ w1, const float* __restrict__ w2,
                         const float* __restrict__ m1w, const float* __restrict__ m1b,
                         const float* __restrict__ m2w, const float* __restrict__ m2b,
                         const float* __restrict__ m3w, const float* __restrict__ m3b)
{
    int t = blockIdx.x*blockDim.x + threadIdx.x;
    const float inv = rsqrtf((float)SD);
    if (t < BB*C1) {
        int b = t / C1, i = t % C1;
        float a = 0.f;
        for (int k = 0; k < SD; k++) a += w1[b*SD+k] * m1w[i*SD+k];
        g_s1[t] = a*inv + m1b[i];
    } else if (t < BB*C1 + BB*C2) {
        int u = t - BB*C1; int b = u / C2, i = u % C2;
        float a = 0.f;
        for (int k = 0; k < SD; k++) a += w2[b*SD+k] * m2w[i*SD+k];
        g_s2[u] = a*inv + m2b[i];
    } else if (t < BB*C1 + 2*BB*C2) {
        int u = t - BB*C1 - BB*C2; int b = u / C2, i = u % C2;
        float a = 0.f;
        for (int k = 0; k < SD; k++) a += w2[b*SD+k] * m3w[i*SD+k];
        g_s3[u] = a*inv + m3b[i];
    }
}

// ---------------- per-(o,i) sum of squared taps ----------------
__global__ void k_wsq(const float* __restrict__ w1c, const float* __restrict__ w2c)
{
    int t = blockIdx.x*blockDim.x + threadIdx.x;
    if (t < C2*C1) {
        float a = 0.f;
        #pragma unroll
        for (int k = 0; k < 9; k++) { float v = w1c[t*9+k]; a += v*v; }
        g_wsq1[t] = a;
    } else if (t < C2*C1 + C2*C2) {
        int u = t - C2*C1;
        float a = 0.f;
        #pragma unroll
        for (int k = 0; k < 9; k++) { float v = w2c[u*9+k]; a += v*v; }
        g_wsq2[u] = a;
    }
}

// ---------------- demod scalars ----------------
__global__ void k_demod()
{
    int t = blockIdx.x*blockDim.x + threadIdx.x;
    const float sc1 = rsqrtf((float)(C1*9));
    const float sc2 = rsqrtf((float)(C2*9));
    if (t < BB*C2) {
        int b = t / C2, o = t % C2;
        float a = 0.f;
        for (int i = 0; i < C1; i++) { float s = g_s1[b*C1+i]; a += g_wsq1[o*C1+i]*s*s; }
        g_e1[t] = sc1 * rsqrtf(sc1*sc1*a + 1e-8f);
    } else if (t < 2*BB*C2) {
        int u = t - BB*C2; int b = u / C2, o = u % C2;
        float a = 0.f;
        for (int i = 0; i < C2; i++) { float s = g_s2[b*C2+i]; a += g_wsq2[o*C2+i]*s*s; }
        g_e2[u] = sc2 * rsqrtf(sc2*sc2*a + 1e-8f);
    }
}

// ---------------- weight transpose: wt[ci][tap][o] = w[o][ci][tap] ----------------
__global__ void k_wtr(const float* __restrict__ w, float* __restrict__ wt, int CIN)
{
    int t = blockIdx.x*blockDim.x + threadIdx.x;
    if (t >= CIN*9*C2) return;
    int o = t % C2, tp = (t/C2) % 9, ci = t/(9*C2);
    wt[t] = w[((size_t)o*CIN + ci)*9 + tp];
}

// ---------------- bilinear 2x upsample * s1 (2 X-pixels per thread, float2 store) ----------------
__global__ void k_upmod(const float* __restrict__ x)
{
    size_t t = (size_t)blockIdx.x*blockDim.x + threadIdx.x;
    if (t >= (size_t)BB*C1*NPIX/2) return;
    int ph = (int)(t % (NPIX/2));
    int bc = (int)(t / (NPIX/2));
    int Y = ph >> 6;
    int tX = ph & 63;
    float sy = Y*0.5f - 0.25f;
    int y0 = (int)floorf(sy); float fy = sy - (float)y0;
    int y0c = max(y0, 0), y1c = min(y0+1, H0-1);
    const float* xp = x + (size_t)bc*NPIX0;
    const float* r0 = xp + y0c*H0;
    const float* r1 = xp + y1c*H0;
    float s = g_s1[bc];
    int xm = max(tX-1, 0), xc = tX, xpn = min(tX+1, H0-1);
    float a0 = r0[xm], a1 = r0[xc], a2 = r0[xpn];
    float b0 = r1[xm], b1 = r1[xc], b2 = r1[xpn];
    float top0 = 0.25f*a0 + 0.75f*a1;
    float bot0 = 0.25f*b0 + 0.75f*b1;
    float top1 = 0.75f*a1 + 0.25f*a2;
    float bot1 = 0.75f*b1 + 0.25f*b2;
    float v0 = ((1.f-fy)*top0 + fy*bot0) * s;
    float v1 = ((1.f-fy)*top1 + fy*bot1) * s;
    *reinterpret_cast<float2*>(&g_up[(size_t)bc*NPIX + Y*H1 + tX*2]) = make_float2(v0, v1);
}

// ---------------- 3x3 conv, cp.async double-buffered, cheap 16B fill ----------------
// CTA: 32 o-chans x (32x8) pixels. 128 threads. Inputs RAW (modulation pre-folded).
// sIn rows stride 40 floats (160B): cols 4..35 = gx0..gx0+31 (8x cp16, 16B-aligned dst
// and 128B-aligned src), col 3 = gx0-1 halo, col 36 = gx0+32 halo (cp4). Zero-fill OOB
// via cp.async src-size operand. Compute reads col tx+kx+3 (stride-1, conflict-free).
#define KC 8
#define TO 32
#define RS 40                  // row stride (floats)
#define SIN_SZ (KC*10*RS)      // 3200 floats per buffer

template<int CIN, bool MULS2>
__global__ __launch_bounds__(128, 4)
void k_conv3x3(const float* __restrict__ in, const float* __restrict__ wt,
               const float* __restrict__ emod, const float* __restrict__ smod2,
               const float* __restrict__ noise, const float* __restrict__ nw,
               float* __restrict__ out)
{
    __shared__ __align__(16) float sIn[2][SIN_SZ];     // 25600 B
    __shared__ __align__(16) float sW[2][KC*9*TO];     // 18432 B

    int tid = threadIdx.x;
    int po  = tid >> 5;
    int tx  = tid & 31;
    int bz  = blockIdx.z;
    int b   = bz >> 3;
    int o0  = (bz & 7) * TO;
    int gx0 = blockIdx.x * 32;
    int gy0 = blockIdx.y * 8;
    const int NCHUNK = CIN / KC;
    const bool haloL = (gx0 > 0), haloR = (gx0 + 32 < H1);

    uint32_t sIn_a = smem_u32(&sIn[0][0]);
    uint32_t sW_a  = smem_u32(&sW[0][0]);

    const float* inB = in + (size_t)b*CIN*NPIX;

    auto fill = [&](int k, int buf) {
        int ci0 = k*KC;
        // 800 ops: row_id (0..79) = c*10 + r, op 0..7 = interior cp16, 8/9 = halo cp4
        for (int i = tid; i < KC*10*10; i += 128) {
            int row_id = i / 10, op = i % 10;
            int c = row_id / 10, r = row_id % 10;
            int gy = gy0 + r - 1;
            bool okY = ((unsigned)gy < H1);
            int gyc = okY ? gy : 0;
            const float* rowp = inB + (size_t)(ci0 + c)*NPIX + gyc*H1;
            uint32_t dstrow = sIn_a + (uint32_t)(buf*SIN_SZ + row_id*RS)*4u;
            if (op < 8) {
                cp16z(dstrow + (4 + op*4)*4, rowp + gx0 + op*4, okY ? 16u : 0u);
            } else if (op == 8) {
                cp4(dstrow + 3*4, rowp + gx0 - (haloL ? 1 : 0), (okY && haloL) ? 4u : 0u);
            } else {
                cp4(dstrow + 36*4, rowp + gx0 + (haloR ? 32 : 0), (okY && haloR) ? 4u : 0u);
            }
        }
        for (int idx = tid; idx < KC*9*8; idx += 128) {
            int row = idx >> 3, v = idx & 7;
            const float* src = wt + ((size_t)ci0*9 + row)*C2 + o0 + v*4;
            cp16(sW_a + (uint32_t)(buf*(KC*9*TO) + row*TO + v*4)*4u, src);
        }
        CP_COMMIT();
    };

    ull acc2[4][8];
    #pragma unroll
    for (int q = 0; q < 4; q++)
        #pragma unroll
        for (int j = 0; j < 8; j++) acc2[q][j] = 0ULL;

    fill(0, 0);

    for (int k = 0; k < NCHUNK; k++) {
        int buf = k & 1;
        asm volatile("cp.async.wait_group 0;" ::: "memory");
        __syncthreads();
        if (k + 1 < NCHUNK) fill(k + 1, buf ^ 1);

        const float* bI = &sIn[buf][0];
        const float* bW = &sW[buf][0];
        #pragma unroll
        for (int c = 0; c < KC; c++) {
            const float* pI = bI + c*10*RS;
            const float* pW = bW + c*9*TO;
            #pragma unroll
            for (int kx = 0; kx < 3; kx++) {
                ull vb[10];
                #pragma unroll
                for (int r = 0; r < 10; r++) vb[r] = bcast2(pI[r*RS + tx + kx + 3]);
                #pragma unroll
                for (int ky = 0; ky < 3; ky++) {
                    ull wp[4];
                    #pragma unroll
                    for (int q = 0; q < 4; q++)
                        wp[q] = *reinterpret_cast<const ull*>(&pW[(ky*3+kx)*TO + po*8 + q*2]);
                    #pragma unroll
                    for (int q = 0; q < 4; q++)
                        #pragma unroll
                        for (int j = 0; j < 8; j++)
                            ffma2(acc2[q][j], wp[q], vb[ky + j]);
                }
            }
        }
    }

    float nwv = nw[0];
    #pragma unroll
    for (int j = 0; j < 8; j++) {
        int gy = gy0 + j, gx = gx0 + tx;
        float nz = nwv * noise[(size_t)b*NPIX + gy*H1 + gx];
        #pragma unroll
        for (int q = 0; q < 4; q++) {
            int o = o0 + po*8 + q*2;
            float a0, a1; unpack2(acc2[q][j], a0, a1);
            float e0 = emod[b*C2 + o], e1 = emod[b*C2 + o + 1];
            float v0 = a0*e0 + nz; v0 = (v0 > 0.f) ? v0 : 0.2f*v0;
            float v1 = a1*e1 + nz; v1 = (v1 > 0.f) ? v1 : 0.2f*v1;
            if (MULS2) {
                v0 *= smod2[b*C2 + o];
                v1 *= smod2[b*C2 + o + 1];
            }
            out[(size_t)(b*C2 + o    )*NPIX + gy*H1 + gx] = v0;
            out[(size_t)(b*C2 + o + 1)*NPIX + gy*H1 + gx] = v1;
        }
    }
}

// ---------------- to_rgb 1x1 (no demod) + upsampled skip ----------------
__global__ void k_rgb(const float* __restrict__ h, const float* __restrict__ rgbw,
                      const float* __restrict__ skip, float* __restrict__ outrgb)
{
    int b = blockIdx.y;
    __shared__ float sw[3][C2];
    for (int i = threadIdx.x; i < 3*C2; i += blockDim.x) {
        int c = i / C2, o = i % C2;
        sw[c][o] = rgbw[c*C2 + o] * g_s3[b*C2 + o] * 0.0625f;  // 1/sqrt(256)
    }
    __syncthreads();
    int p = blockIdx.x*blockDim.x + threadIdx.x;
    float a0 = 0.f, a1 = 0.f, a2 = 0.f;
    for (int o = 0; o < C2; o++) {
        float v = h[(size_t)(b*C2 + o)*NPIX + p];
        a0 += sw[0][o]*v; a1 += sw[1][o]*v; a2 += sw[2][o]*v;
    }
    int X = p % H1, Y = p / H1;
    float sy = Y*0.5f - 0.25f, sx = X*0.5f - 0.25f;
    int y0 = (int)floorf(sy), x0 = (int)floorf(sx);
    float fy = sy - (float)y0, fx = sx - (float)x0;
    int y0c = max(y0, 0), y1c = min(y0+1, H0-1);
    int x0c = max(x0, 0), x1c = min(x0+1, H0-1);
    float a[3] = {a0, a1, a2};
    #pragma unroll
    for (int c = 0; c < 3; c++) {
        const float* sp = skip + (size_t)(b*3 + c)*NPIX0;
        float bv = (1.f-fy)*((1.f-fx)*sp[y0c*H0+x0c] + fx*sp[y0c*H0+x1c])
                 +      fy *((1.f-fx)*sp[y1c*H0+x0c] + fx*sp[y1c*H0+x1c]);
        outrgb[(size_t)(b*3 + c)*NPIX + p] = a[c] + bv;
    }
}

// ---------------- launch ----------------
extern "C" void kernel_launch(void* const* d_in, const int* in_sizes, int n_in,
                              void* d_out, int out_size)
{
    const float* x       = (const float*)d_in[0];
    const float* w1      = (const float*)d_in[1];
    const float* w2      = (const float*)d_in[2];
    const float* skip    = (const float*)d_in[3];
    const float* noise1  = (const float*)d_in[4];
    const float* noise2  = (const float*)d_in[5];
    const float* conv1_w = (const float*)d_in[6];
    const float* mod1_w  = (const float*)d_in[7];
    const float* mod1_b  = (const float*)d_in[8];
    const float* conv2_w = (const float*)d_in[9];
    const float* mod2_w  = (const float*)d_in[10];
    const float* mod2_b  = (const float*)d_in[11];
    const float* rgb_w   = (const float*)d_in[12];
    const float* mod3_w  = (const float*)d_in[13];
    const float* mod3_b  = (const float*)d_in[14];
    const float* nw1     = (const float*)d_in[15];
    const float* nw2     = (const float*)d_in[16];
    float* out = (float*)d_out;

    void *p_up, *p_h1, *p_e1, *p_e2, *p_s2, *p_wt1, *p_wt2;
    cudaGetSymbolAddress(&p_up, g_up);
    cudaGetSymbolAddress(&p_h1, g_h1);
    cudaGetSymbolAddress(&p_e1, g_e1);
    cudaGetSymbolAddress(&p_e2, g_e2);
    cudaGetSymbolAddress(&p_s2, g_s2);
    cudaGetSymbolAddress(&p_wt1, g_wt1);
    cudaGetSymbolAddress(&p_wt2, g_wt2);

    float* out_h   = out;                                // [8,256,128,128]
    float* out_rgb = out + (size_t)BB*C2*NPIX;           // [8,3,128,128]

    // 1. styles
    {
        int n = BB*C1 + 2*BB*C2;
        k_styles<<<(n + 255)/256, 256>>>(w1, w2, mod1_w, mod1_b, mod2_w, mod2_b, mod3_w, mod3_b);
    }
    // 2. weight square sums + demod scalars
    {
        int n = C2*C1 + C2*C2;
        k_wsq<<<(n + 255)/256, 256>>>(conv1_w, conv2_w);
    }
    k_demod<<<(2*BB*C2 + 255)/256, 256>>>();
    // 3. weight transposes
    k_wtr<<<(C1*9*C2 + 255)/256, 256>>>(conv1_w, (float*)p_wt1, C1);
    k_wtr<<<(C2*9*C2 + 255)/256, 256>>>(conv2_w, (float*)p_wt2, C2);
    // 4. upsample + modulate (s1), 2 px/thread
    {
        size_t n = (size_t)BB*C1*NPIX/2;
        k_upmod<<<(unsigned)((n + 255)/256), 256>>>(x);
    }
    // 5. conv1 -> g_h1 (epilogue: e1, noise1, lrelu, then * s2 for conv2's input)
    k_conv3x3<C1, true ><<<dim3(4, 16, BB*8), 128>>>(
        (const float*)p_up, (const float*)p_wt1,
        (const float*)p_e1, (const float*)p_s2, noise1, nw1, (float*)p_h1);
    // 6. conv2 (raw input) -> d_out h region
    k_conv3x3<C2, false><<<dim3(4, 16, BB*8), 128>>>(
        (const float*)p_h1, (const float*)p_wt2,
        (const float*)p_e2, nullptr, noise2, nw2, out_h);
    // 7. to_rgb + upsampled skip
    k_rgb<<<dim3(NPIX/256, BB), 256>>>(out_h, rgb_w, skip, out_rgb);
}

// round 14
// speedup vs baseline: 2.2990x; 1.7335x over previous
#include <cuda_runtime.h>
#include <math.h>
#include <stdint.h>

#define BB   8
#define C1   512
#define C2   256
#define SD   512
#define H0   64
#define H1   128
#define NPIX   (H1*H1)      // 16384
#define NPIX0  (H0*H0)      // 4096
#define NT   32768          // total 2x2 output tiles: 8 b * 64 * 64

typedef unsigned long long ull;

__device__ __forceinline__ void ffma2(ull& acc, ull a, ull b) {
    asm("fma.rn.f32x2 %0, %1, %2, %0;" : "+l"(acc) : "l"(a), "l"(b));
}
__device__ __forceinline__ ull bcast2(float v) {
    ull p;
    asm("mov.b64 %0, {%1, %1};" : "=l"(p) : "r"(__float_as_uint(v)));
    return p;
}
__device__ __forceinline__ void unpack2(ull p, float& lo, float& hi) {
    unsigned int a, b;
    asm("mov.b64 {%0, %1}, %2;" : "=r"(a), "=r"(b) : "l"(p));
    lo = __uint_as_float(a); hi = __uint_as_float(b);
}
__device__ __forceinline__ uint32_t smem_u32(const void* p) {
    uint32_t a;
    asm("{ .reg .u64 t; cvta.to.shared.u64 t, %1; cvt.u32.u64 %0, t; }" : "=r"(a) : "l"(p));
    return a;
}
__device__ __forceinline__ void cp16(uint32_t dst, const float* src) {
    asm volatile("cp.async.ca.shared.global [%0], [%1], 16;" :: "r"(dst), "l"(src));
}
#define CP_COMMIT() asm volatile("cp.async.commit_group;")

// ---------------- scratch (device globals; no allocation) ----------------
__device__ float g_s1[BB*C1];
__device__ float g_s2[BB*C2];
__device__ float g_s3[BB*C2];
__device__ float g_e1[BB*C2];
__device__ float g_e2[BB*C2];
__device__ float g_wsq1[C2*C1];
__device__ float g_wsq2[C2*C2];
__device__ float g_up [(size_t)BB*C1*NPIX];        // 268 MB upsampled*s1 input
__device__ float g_h1 [(size_t)BB*C2*NPIX];        // 134 MB conv1 out * s2
__device__ float g_U1 [(size_t)16*C1*C2];          // 8.4 MB winograd weights conv1 [t][ci][o]
__device__ float g_U2 [(size_t)16*C2*C2];          // 4.2 MB
__device__ float g_V  [(size_t)16*C1*NT];          // 1.07 GB transformed input [t][ci][tile]
__device__ float g_M  [(size_t)16*C2*NT];          // 537 MB GEMM out [t][o][tile]

// ---------------- styles ----------------
__global__ void k_styles(const float* __restrict__ w1, const float* __restrict__ w2,
                         const float* __restrict__ m1w, const float* __restrict__ m1b,
                         const float* __restrict__ m2w, const float* __restrict__ m2b,
                         const float* __restrict__ m3w, const float* __restrict__ m3b)
{
    int t = blockIdx.x*blockDim.x + threadIdx.x;
    const float inv = rsqrtf((float)SD);
    if (t < BB*C1) {
        int b = t / C1, i = t % C1;
        float a = 0.f;
        for (int k = 0; k < SD; k++) a += w1[b*SD+k] * m1w[i*SD+k];
        g_s1[t] = a*inv + m1b[i];
    } else if (t < BB*C1 + BB*C2) {
        int u = t - BB*C1; int b = u / C2, i = u % C2;
        float a = 0.f;
        for (int k = 0; k < SD; k++) a += w2[b*SD+k] * m2w[i*SD+k];
        g_s2[u] = a*inv + m2b[i];
    } else if (t < BB*C1 + 2*BB*C2) {
        int u = t - BB*C1 - BB*C2; int b = u / C2, i = u % C2;
        float a = 0.f;
        for (int k = 0; k < SD; k++) a += w2[b*SD+k] * m3w[i*SD+k];
        g_s3[u] = a*inv + m3b[i];
    }
}

// ---------------- per-(o,i) sum of squared taps ----------------
__global__ void k_wsq(const float* __restrict__ w1c, const float* __restrict__ w2c)
{
    int t = blockIdx.x*blockDim.x + threadIdx.x;
    if (t < C2*C1) {
        float a = 0.f;
        #pragma unroll
        for (int k = 0; k < 9; k++) { float v = w1c[t*9+k]; a += v*v; }
        g_wsq1[t] = a;
    } else if (t < C2*C1 + C2*C2) {
        int u = t - C2*C1;
        float a = 0.f;
        #pragma unroll
        for (int k = 0; k < 9; k++) { float v = w2c[u*9+k]; a += v*v; }
        g_wsq2[u] = a;
    }
}

// ---------------- demod scalars ----------------
__global__ void k_demod()
{
    int t = blockIdx.x*blockDim.x + threadIdx.x;
    const float sc1 = rsqrtf((float)(C1*9));
    const float sc2 = rsqrtf((float)(C2*9));
    if (t < BB*C2) {
        int b = t / C2, o = t % C2;
        float a = 0.f;
        for (int i = 0; i < C1; i++) { float s = g_s1[b*C1+i]; a += g_wsq1[o*C1+i]*s*s; }
        g_e1[t] = sc1 * rsqrtf(sc1*sc1*a + 1e-8f);
    } else if (t < 2*BB*C2) {
        int u = t - BB*C2; int b = u / C2, o = u % C2;
        float a = 0.f;
        for (int i = 0; i < C2; i++) { float s = g_s2[b*C2+i]; a += g_wsq2[o*C2+i]*s*s; }
        g_e2[u] = sc2 * rsqrtf(sc2*sc2*a + 1e-8f);
    }
}

// ---------------- winograd weight transform: U[t][ci][o] = (G g G^T)[t] ----------------
__global__ void k_wt(const float* __restrict__ w, float* __restrict__ U, int CIN)
{
    int idx = blockIdx.x*256 + threadIdx.x;
    if (idx >= CIN*C2) return;
    int o = idx & 255, ci = idx >> 8;
    const float* g = w + ((size_t)o*CIN + ci)*9;   // g[ky*3+kx]
    float a[4][3];
    #pragma unroll
    for (int c = 0; c < 3; c++) {
        float g0 = g[c], g1 = g[3+c], g2 = g[6+c];
        a[0][c] = g0;
        a[1][c] = 0.5f*(g0 + g1 + g2);
        a[2][c] = 0.5f*(g0 - g1 + g2);
        a[3][c] = g2;
    }
    #pragma unroll
    for (int i = 0; i < 4; i++) {
        float u0 = a[i][0], u1 = 0.5f*(a[i][0]+a[i][1]+a[i][2]),
              u2 = 0.5f*(a[i][0]-a[i][1]+a[i][2]), u3 = a[i][2];
        U[((size_t)(i*4+0)*CIN + ci)*C2 + o] = u0;
        U[((size_t)(i*4+1)*CIN + ci)*C2 + o] = u1;
        U[((size_t)(i*4+2)*CIN + ci)*C2 + o] = u2;
        U[((size_t)(i*4+3)*CIN + ci)*C2 + o] = u3;
    }
}

// ---------------- bilinear 2x upsample * s1 (2 X-pixels per thread) ----------------
__global__ void k_upmod(const float* __restrict__ x)
{
    size_t t = (size_t)blockIdx.x*blockDim.x + threadIdx.x;
    if (t >= (size_t)BB*C1*NPIX/2) return;
    int ph = (int)(t % (NPIX/2));
    int bc = (int)(t / (NPIX/2));
    int Y = ph >> 6;
    int tX = ph & 63;
    float sy = Y*0.5f - 0.25f;
    int y0 = (int)floorf(sy); float fy = sy - (float)y0;
    int y0c = max(y0, 0), y1c = min(y0+1, H0-1);
    const float* xp = x + (size_t)bc*NPIX0;
    const float* r0 = xp + y0c*H0;
    const float* r1 = xp + y1c*H0;
    float s = g_s1[bc];
    int xm = max(tX-1, 0), xc = tX, xpn = min(tX+1, H0-1);
    float a0 = r0[xm], a1 = r0[xc], a2 = r0[xpn];
    float b0 = r1[xm], b1 = r1[xc], b2 = r1[xpn];
    float top0 = 0.25f*a0 + 0.75f*a1;
    float bot0 = 0.25f*b0 + 0.75f*b1;
    float top1 = 0.75f*a1 + 0.25f*a2;
    float bot1 = 0.75f*b1 + 0.25f*b2;
    float v0 = ((1.f-fy)*top0 + fy*bot0) * s;
    float v1 = ((1.f-fy)*top1 + fy*bot1) * s;
    *reinterpret_cast<float2*>(&g_up[(size_t)bc*NPIX + Y*H1 + tX*2]) = make_float2(v0, v1);
}

// ---------------- input transform: V[t][ci][tile] = (B^T d B)[t], pad=1 zeros ----------------
__global__ void k_itrans(const float* __restrict__ in, float* __restrict__ V, int CIN)
{
    int idx = blockIdx.x*256 + threadIdx.x;    // (ci, b, ty, txt); txt fastest
    if (idx >= CIN*NT) return;
    int txt = idx & 63, ty = (idx >> 6) & 63, b = (idx >> 12) & 7, ci = idx >> 15;
    const float* src = in + ((size_t)(b*CIN + ci) << 14);
    int r0 = 2*ty - 1, c0 = 2*txt - 1;
    float d[4][4];
    #pragma unroll
    for (int r = 0; r < 4; r++) {
        int y = r0 + r;
        bool oy = ((unsigned)y < (unsigned)H1);
        const float* rowp = src + (oy ? y*H1 : 0);
        #pragma unroll
        for (int c = 0; c < 4; c++) {
            int xx = c0 + c;
            d[r][c] = (oy && (unsigned)xx < (unsigned)H1) ? rowp[xx] : 0.f;
        }
    }
    // rows: B^T d
    float tr[4][4];
    #pragma unroll
    for (int c = 0; c < 4; c++) {
        tr[0][c] = d[0][c] - d[2][c];
        tr[1][c] = d[1][c] + d[2][c];
        tr[2][c] = d[2][c] - d[1][c];
        tr[3][c] = d[1][c] - d[3][c];
    }
    int tile = idx & 32767;   // (b<<12)|(ty<<6)|txt
    #pragma unroll
    for (int r = 0; r < 4; r++) {
        float v0 = tr[r][0] - tr[r][2];
        float v1 = tr[r][1] + tr[r][2];
        float v2 = tr[r][2] - tr[r][1];
        float v3 = tr[r][1] - tr[r][3];
        V[((size_t)(r*4+0)*CIN + ci)*NT + tile] = v0;
        V[((size_t)(r*4+1)*CIN + ci)*NT + tile] = v1;
        V[((size_t)(r*4+2)*CIN + ci)*NT + tile] = v2;
        V[((size_t)(r*4+3)*CIN + ci)*NT + tile] = v3;
    }
}

// ---------------- winograd GEMM: M[t][o][tile] = sum_ci U[t][ci][o] * V[t][ci][tile] ----------------
// CTA: 32 o x 256 tiles, 128 threads (po=tid/32: 8 o each as 4 pairs; tx: 8 tiles).
#define GKC 8
template<int CIN>
__global__ __launch_bounds__(128, 4)
void k_gemm(const float* __restrict__ U, const float* __restrict__ V, float* __restrict__ M)
{
    __shared__ __align__(16) float sV[2][GKC*256];   // 16 KB
    __shared__ __align__(16) float sU[2][GKC*32];    // 2 KB

    int tid = threadIdx.x;
    int po  = tid >> 5;
    int tx  = tid & 31;
    int tile0 = blockIdx.x * 256;
    int o0    = blockIdx.y * 32;
    int tap   = blockIdx.z;

    const float* Vt = V + (size_t)tap*CIN*NT;
    const float* Ut = U + (size_t)tap*CIN*C2;
    uint32_t sV_a = smem_u32(&sV[0][0]);
    uint32_t sU_a = smem_u32(&sU[0][0]);

    auto fill = [&](int k, int buf) {
        int ci0 = k*GKC;
        for (int i = tid; i < GKC*64; i += 128) {        // 512 cp16: 8ci x 256 tiles
            int ci = i >> 6, v = i & 63;
            cp16(sV_a + (uint32_t)(buf*(GKC*256) + ci*256 + v*4)*4u,
                 Vt + (size_t)(ci0+ci)*NT + tile0 + v*4);
        }
        if (tid < 64) {                                   // 64 cp16: 8ci x 32 o
            int ci = tid >> 3, v = tid & 7;
            cp16(sU_a + (uint32_t)(buf*(GKC*32) + ci*32 + v*4)*4u,
                 Ut + (size_t)(ci0+ci)*C2 + o0 + v*4);
        }
        CP_COMMIT();
    };

    ull acc2[4][8];
    #pragma unroll
    for (int q = 0; q < 4; q++)
        #pragma unroll
        for (int j = 0; j < 8; j++) acc2[q][j] = 0ULL;

    fill(0, 0);

    const int NCHUNK = CIN / GKC;
    for (int k = 0; k < NCHUNK; k++) {
        int buf = k & 1;
        asm volatile("cp.async.wait_group 0;" ::: "memory");
        __syncthreads();
        if (k + 1 < NCHUNK) fill(k + 1, buf ^ 1);

        const float* bV = &sV[buf][0];
        const float* bU = &sU[buf][0];
        #pragma unroll
        for (int ci = 0; ci < GKC; ci++) {
            ull vb[8];
            #pragma unroll
            for (int j = 0; j < 8; j++) vb[j] = bcast2(bV[ci*256 + tx + 32*j]);
            ull wp[4];
            #pragma unroll
            for (int q = 0; q < 4; q++)
                wp[q] = *reinterpret_cast<const ull*>(&bU[ci*32 + po*8 + q*2]);
            #pragma unroll
            for (int q = 0; q < 4; q++)
                #pragma unroll
                for (int j = 0; j < 8; j++)
                    ffma2(acc2[q][j], wp[q], vb[j]);
        }
    }

    float* Mt = M + (size_t)tap*C2*NT;
    #pragma unroll
    for (int q = 0; q < 4; q++) {
        int o = o0 + po*8 + q*2;
        #pragma unroll
        for (int j = 0; j < 8; j++) {
            float a0, a1; unpack2(acc2[q][j], a0, a1);
            Mt[(size_t)o*NT     + tile0 + tx + 32*j] = a0;
            Mt[(size_t)(o+1)*NT + tile0 + tx + 32*j] = a1;
        }
    }
}

// ---------------- inverse transform + epilogue: Y = A^T M A; e, noise, lrelu, (*s2) ----------------
template<bool MULS2>
__global__ void k_inv(const float* __restrict__ emod, const float* __restrict__ smod2,
                      const float* __restrict__ noise, const float* __restrict__ nw,
                      float* __restrict__ out)
{
    int idx = blockIdx.x*256 + threadIdx.x;    // (o, b, ty, txt); txt fastest
    if (idx >= C2*NT) return;
    int txt = idx & 63, ty = (idx >> 6) & 63, b = (idx >> 12) & 7, o = idx >> 15;
    int tile = idx & 32767;
    float m[16];
    #pragma unroll
    for (int t = 0; t < 16; t++)
        m[t] = g_M[((size_t)t*C2 + o)*NT + tile];
    float s0[4], s1[4];
    #pragma unroll
    for (int c = 0; c < 4; c++) {
        s0[c] = m[c] + m[4+c] + m[8+c];
        s1[c] = m[4+c] - m[8+c] - m[12+c];
    }
    float y00 = s0[0]+s0[1]+s0[2], y01 = s0[1]-s0[2]-s0[3];
    float y10 = s1[0]+s1[1]+s1[2], y11 = s1[1]-s1[2]-s1[3];

    int Y0 = 2*ty, X0 = 2*txt;
    float e = emod[b*C2 + o];
    float nwv = nw[0];
    float s2v = MULS2 ? smod2[b*C2 + o] : 1.f;
    const float* nz = noise + ((size_t)b << 14);
    float* dst = out + ((size_t)(b*C2 + o) << 14);

    float v;
    v = y00*e + nwv*nz[Y0*H1 + X0];       v = (v>0.f)?v:0.2f*v; float r00 = v*s2v;
    v = y01*e + nwv*nz[Y0*H1 + X0+1];     v = (v>0.f)?v:0.2f*v; float r01 = v*s2v;
    v = y10*e + nwv*nz[(Y0+1)*H1 + X0];   v = (v>0.f)?v:0.2f*v; float r10 = v*s2v;
    v = y11*e + nwv*nz[(Y0+1)*H1 + X0+1]; v = (v>0.f)?v:0.2f*v; float r11 = v*s2v;
    *reinterpret_cast<float2*>(&dst[Y0*H1 + X0])     = make_float2(r00, r01);
    *reinterpret_cast<float2*>(&dst[(Y0+1)*H1 + X0]) = make_float2(r10, r11);
}

// ---------------- to_rgb 1x1 (no demod) + upsampled skip ----------------
__global__ void k_rgb(const float* __restrict__ h, const float* __restrict__ rgbw,
                      const float* __restrict__ skip, float* __restrict__ outrgb)
{
    int b = blockIdx.y;
    __shared__ float sw[3][C2];
    for (int i = threadIdx.x; i < 3*C2; i += blockDim.x) {
        int c = i / C2, o = i % C2;
        sw[c][o] = rgbw[c*C2 + o] * g_s3[b*C2 + o] * 0.0625f;  // 1/sqrt(256)
    }
    __syncthreads();
    int p = blockIdx.x*blockDim.x + threadIdx.x;
    float a0 = 0.f, a1 = 0.f, a2 = 0.f;
    for (int o = 0; o < C2; o++) {
        float v = h[(size_t)(b*C2 + o)*NPIX + p];
        a0 += sw[0][o]*v; a1 += sw[1][o]*v; a2 += sw[2][o]*v;
    }
    int X = p % H1, Y = p / H1;
    float sy = Y*0.5f - 0.25f, sx = X*0.5f - 0.25f;
    int y0 = (int)floorf(sy), x0 = (int)floorf(sx);
    float fy = sy - (float)y0, fx = sx - (float)x0;
    int y0c = max(y0, 0), y1c = min(y0+1, H0-1);
    int x0c = max(x0, 0), x1c = min(x0+1, H0-1);
    float a[3] = {a0, a1, a2};
    #pragma unroll
    for (int c = 0; c < 3; c++) {
        const float* sp = skip + (size_t)(b*3 + c)*NPIX0;
        float bv = (1.f-fy)*((1.f-fx)*sp[y0c*H0+x0c] + fx*sp[y0c*H0+x1c])
                 +      fy *((1.f-fx)*sp[y1c*H0+x0c] + fx*sp[y1c*H0+x1c]);
        outrgb[(size_t)(b*3 + c)*NPIX + p] = a[c] + bv;
    }
}

// ---------------- launch ----------------
extern "C" void kernel_launch(void* const* d_in, const int* in_sizes, int n_in,
                              void* d_out, int out_size)
{
    const float* x       = (const float*)d_in[0];
    const float* w1      = (const float*)d_in[1];
    const float* w2      = (const float*)d_in[2];
    const float* skip    = (const float*)d_in[3];
    const float* noise1  = (const float*)d_in[4];
    const float* noise2  = (const float*)d_in[5];
    const float* conv1_w = (const float*)d_in[6];
    const float* mod1_w  = (const float*)d_in[7];
    const float* mod1_b  = (const float*)d_in[8];
    const float* conv2_w = (const float*)d_in[9];
    const float* mod2_w  = (const float*)d_in[10];
    const float* mod2_b  = (const float*)d_in[11];
    const float* rgb_w   = (const float*)d_in[12];
    const float* mod3_w  = (const float*)d_in[13];
    const float* mod3_b  = (const float*)d_in[14];
    const float* nw1     = (const float*)d_in[15];
    const float* nw2     = (const float*)d_in[16];
    float* out = (float*)d_out;

    void *p_up, *p_h1, *p_e1, *p_e2, *p_s2, *p_U1, *p_U2, *p_V, *p_M;
    cudaGetSymbolAddress(&p_up, g_up);
    cudaGetSymbolAddress(&p_h1, g_h1);
    cudaGetSymbolAddress(&p_e1, g_e1);
    cudaGetSymbolAddress(&p_e2, g_e2);
    cudaGetSymbolAddress(&p_s2, g_s2);
    cudaGetSymbolAddress(&p_U1, g_U1);
    cudaGetSymbolAddress(&p_U2, g_U2);
    cudaGetSymbolAddress(&p_V,  g_V);
    cudaGetSymbolAddress(&p_M,  g_M);

    float* out_h   = out;                                // [8,256,128,128]
    float* out_rgb = out + (size_t)BB*C2*NPIX;           // [8,3,128,128]

    // 1. styles + demod scalars
    {
        int n = BB*C1 + 2*BB*C2;
        k_styles<<<(n + 255)/256, 256>>>(w1, w2, mod1_w, mod1_b, mod2_w, mod2_b, mod3_w, mod3_b);
    }
    {
        int n = C2*C1 + C2*C2;
        k_wsq<<<(n + 255)/256, 256>>>(conv1_w, conv2_w);
    }
    k_demod<<<(2*BB*C2 + 255)/256, 256>>>();
    // 2. winograd weight transforms
    k_wt<<<(C1*C2 + 255)/256, 256>>>(conv1_w, (float*)p_U1, C1);
    k_wt<<<(C2*C2 + 255)/256, 256>>>(conv2_w, (float*)p_U2, C2);
    // 3. upsample + modulate(s1)
    {
        size_t n = (size_t)BB*C1*NPIX/2;
        k_upmod<<<(unsigned)((n + 255)/256), 256>>>(x);
    }
    // 4. conv1 via winograd
    k_itrans<<<(C1*NT)/256, 256>>>((const float*)p_up, (float*)p_V, C1);
    k_gemm<C1><<<dim3(NT/256, C2/32, 16), 128>>>((const float*)p_U1, (const float*)p_V, (float*)p_M);
    k_inv<true><<<(C2*NT)/256, 256>>>((const float*)p_e1, (const float*)p_s2, noise1, nw1, (float*)p_h1);
    // 5. conv2 via winograd (reuse V, M)
    k_itrans<<<(C2*NT)/256, 256>>>((const float*)p_h1, (float*)p_V, C2);
    k_gemm<C2><<<dim3(NT/256, C2/32, 16), 128>>>((const float*)p_U2, (const float*)p_V, (float*)p_M);
    k_inv<false><<<(C2*NT)/256, 256>>>((const float*)p_e2, nullptr, noise2, nw2, out_h);
    // 6. to_rgb + upsampled skip
    k_rgb<<<dim3(NPIX/256, BB), 256>>>(out_h, rgb_w, skip, out_rgb);
}

// round 15
// speedup vs baseline: 3.7660x; 1.6381x over previous
#include <cuda_runtime.h>
#include <math.h>
#include <stdint.h>

#define BB   8
#define C1   512
#define C2   256
#define SD   512
#define H0   64
#define H1   128
#define NPIX   (H1*H1)      // 16384
#define NPIX0  (H0*H0)      // 4096
#define NT4  8192           // 4x4 output tiles: 8 b * 32 * 32

typedef unsigned long long ull;

__device__ __forceinline__ void ffma2(ull& acc, ull a, ull b) {
    asm("fma.rn.f32x2 %0, %1, %2, %0;" : "+l"(acc) : "l"(a), "l"(b));
}
__device__ __forceinline__ ull bcast2(float v) {
    ull p;
    asm("mov.b64 %0, {%1, %1};" : "=l"(p) : "r"(__float_as_uint(v)));
    return p;
}
__device__ __forceinline__ void unpack2(ull p, float& lo, float& hi) {
    unsigned int a, b;
    asm("mov.b64 {%0, %1}, %2;" : "=r"(a), "=r"(b) : "l"(p));
    lo = __uint_as_float(a); hi = __uint_as_float(b);
}
__device__ __forceinline__ uint32_t smem_u32(const void* p) {
    uint32_t a;
    asm("{ .reg .u64 t; cvta.to.shared.u64 t, %1; cvt.u32.u64 %0, t; }" : "=r"(a) : "l"(p));
    return a;
}
__device__ __forceinline__ void cp16(uint32_t dst, const float* src) {
    asm volatile("cp.async.ca.shared.global [%0], [%1], 16;" :: "r"(dst), "l"(src));
}
#define CP_COMMIT() asm volatile("cp.async.commit_group;")

// ---------------- scratch (device globals; no allocation) ----------------
__device__ float g_s1[BB*C1];
__device__ float g_s2[BB*C2];
__device__ float g_s3[BB*C2];
__device__ float g_e1[BB*C2];
__device__ float g_e2[BB*C2];
__device__ float g_wsq1[C2*C1];
__device__ float g_wsq2[C2*C2];
__device__ float g_up [(size_t)BB*C1*NPIX];        // 268 MB upsampled*s1 input
__device__ float g_h1 [(size_t)BB*C2*NPIX];        // 134 MB conv1 out * s2
__device__ float g_U1 [(size_t)36*C1*C2];          // 18.9 MB winograd weights conv1 [t][ci][o]
__device__ float g_U2 [(size_t)36*C2*C2];          // 9.4 MB
__device__ float g_V  [(size_t)36*C1*NT4];         // 604 MB transformed input [t][ci][tile]
__device__ float g_M  [(size_t)36*C2*NT4];         // 302 MB GEMM out [t][o][tile]

// ---------------- styles ----------------
__global__ void k_styles(const float* __restrict__ w1, const float* __restrict__ w2,
                         const float* __restrict__ m1w, const float* __restrict__ m1b,
                         const float* __restrict__ m2w, const float* __restrict__ m2b,
                         const float* __restrict__ m3w, const float* __restrict__ m3b)
{
    int t = blockIdx.x*blockDim.x + threadIdx.x;
    const float inv = rsqrtf((float)SD);
    if (t < BB*C1) {
        int b = t / C1, i = t % C1;
        float a = 0.f;
        for (int k = 0; k < SD; k++) a += w1[b*SD+k] * m1w[i*SD+k];
        g_s1[t] = a*inv + m1b[i];
    } else if (t < BB*C1 + BB*C2) {
        int u = t - BB*C1; int b = u / C2, i = u % C2;
        float a = 0.f;
        for (int k = 0; k < SD; k++) a += w2[b*SD+k] * m2w[i*SD+k];
        g_s2[u] = a*inv + m2b[i];
    } else if (t < BB*C1 + 2*BB*C2) {
        int u = t - BB*C1 - BB*C2; int b = u / C2, i = u % C2;
        float a = 0.f;
        for (int k = 0; k < SD; k++) a += w2[b*SD+k] * m3w[i*SD+k];
        g_s3[u] = a*inv + m3b[i];
    }
}

// ---------------- per-(o,i) sum of squared taps ----------------
__global__ void k_wsq(const float* __restrict__ w1c, const float* __restrict__ w2c)
{
    int t = blockIdx.x*blockDim.x + threadIdx.x;
    if (t < C2*C1) {
        float a = 0.f;
        #pragma unroll
        for (int k = 0; k < 9; k++) { float v = w1c[t*9+k]; a += v*v; }
        g_wsq1[t] = a;
    } else if (t < C2*C1 + C2*C2) {
        int u = t - C2*C1;
        float a = 0.f;
        #pragma unroll
        for (int k = 0; k < 9; k++) { float v = w2c[u*9+k]; a += v*v; }
        g_wsq2[u] = a;
    }
}

// ---------------- demod scalars ----------------
__global__ void k_demod()
{
    int t = blockIdx.x*blockDim.x + threadIdx.x;
    const float sc1 = rsqrtf((float)(C1*9));
    const float sc2 = rsqrtf((float)(C2*9));
    if (t < BB*C2) {
        int b = t / C2, o = t % C2;
        float a = 0.f;
        for (int i = 0; i < C1; i++) { float s = g_s1[b*C1+i]; a += g_wsq1[o*C1+i]*s*s; }
        g_e1[t] = sc1 * rsqrtf(sc1*sc1*a + 1e-8f);
    } else if (t < 2*BB*C2) {
        int u = t - BB*C2; int b = u / C2, o = u % C2;
        float a = 0.f;
        for (int i = 0; i < C2; i++) { float s = g_s2[b*C2+i]; a += g_wsq2[o*C2+i]*s*s; }
        g_e2[u] = sc2 * rsqrtf(sc2*sc2*a + 1e-8f);
    }
}

// ---------------- F(4,3) weight transform: U[t][ci][o] = (G g G^T)[t] ----------------
__global__ void k_wt4(const float* __restrict__ w, float* __restrict__ U, int CIN)
{
    int idx = blockIdx.x*256 + threadIdx.x;
    if (idx >= CIN*C2) return;
    int o = idx & 255, ci = idx >> 8;
    const float* g = w + ((size_t)o*CIN + ci)*9;   // g[ky*3+kx]
    float a[6][3];
    #pragma unroll
    for (int c = 0; c < 3; c++) {
        float g0 = g[c], g1 = g[3+c], g2 = g[6+c];
        a[0][c] = 0.25f*g0;
        a[1][c] = -(g0+g1+g2)*(1.f/6.f);
        a[2][c] = (-g0+g1-g2)*(1.f/6.f);
        a[3][c] = g0*(1.f/24.f) + g1*(1.f/12.f) + g2*(1.f/6.f);
        a[4][c] = g0*(1.f/24.f) - g1*(1.f/12.f) + g2*(1.f/6.f);
        a[5][c] = g2;
    }
    #pragma unroll
    for (int i = 0; i < 6; i++) {
        float b0 = a[i][0], b1 = a[i][1], b2 = a[i][2];
        float u[6];
        u[0] = 0.25f*b0;
        u[1] = -(b0+b1+b2)*(1.f/6.f);
        u[2] = (-b0+b1-b2)*(1.f/6.f);
        u[3] = b0*(1.f/24.f) + b1*(1.f/12.f) + b2*(1.f/6.f);
        u[4] = b0*(1.f/24.f) - b1*(1.f/12.f) + b2*(1.f/6.f);
        u[5] = b2;
        #pragma unroll
        for (int j = 0; j < 6; j++)
            U[((size_t)(i*6+j)*CIN + ci)*C2 + o] = u[j];
    }
}

// ---------------- bilinear 2x upsample * s1 (2 X-pixels per thread) ----------------
__global__ void k_upmod(const float* __restrict__ x)
{
    size_t t = (size_t)blockIdx.x*blockDim.x + threadIdx.x;
    if (t >= (size_t)BB*C1*NPIX/2) return;
    int ph = (int)(t % (NPIX/2));
    int bc = (int)(t / (NPIX/2));
    int Y = ph >> 6;
    int tX = ph & 63;
    float sy = Y*0.5f - 0.25f;
    int y0 = (int)floorf(sy); float fy = sy - (float)y0;
    int y0c = max(y0, 0), y1c = min(y0+1, H0-1);
    const float* xp = x + (size_t)bc*NPIX0;
    const float* r0 = xp + y0c*H0;
    const float* r1 = xp + y1c*H0;
    float s = g_s1[bc];
    int xm = max(tX-1, 0), xc = tX, xpn = min(tX+1, H0-1);
    float a0 = r0[xm], a1 = r0[xc], a2 = r0[xpn];
    float b0 = r1[xm], b1 = r1[xc], b2 = r1[xpn];
    float top0 = 0.25f*a0 + 0.75f*a1;
    float bot0 = 0.25f*b0 + 0.75f*b1;
    float top1 = 0.75f*a1 + 0.25f*a2;
    float bot1 = 0.75f*b1 + 0.25f*b2;
    float v0 = ((1.f-fy)*top0 + fy*bot0) * s;
    float v1 = ((1.f-fy)*top1 + fy*bot1) * s;
    *reinterpret_cast<float2*>(&g_up[(size_t)bc*NPIX + Y*H1 + tX*2]) = make_float2(v0, v1);
}

// ---------------- F(4,3) input transform: V[t][ci][tile] = (B^T d B)[t], pad=1 ----------------
__global__ void k_itrans4(const float* __restrict__ in, float* __restrict__ V, int CIN)
{
    int idx = blockIdx.x*256 + threadIdx.x;    // ci*NT4 + tile; tile = (b<<10)|(ty<<5)|txt
    if (idx >= CIN*NT4) return;
    int txt = idx & 31, ty = (idx >> 5) & 31, b = (idx >> 10) & 7, ci = idx >> 13;
    int tile = idx & (NT4-1);
    const float* src = in + ((size_t)(b*CIN + ci) << 14);
    int r0 = 4*ty - 1, c0 = 4*txt - 1;
    // column transform: t[i][c] = (B^T d)[i][c]
    float t[6][6];
    #pragma unroll
    for (int c = 0; c < 6; c++) {
        int xx = c0 + c;
        bool ox = ((unsigned)xx < (unsigned)H1);
        float d0, d1, d2, d3, d4, d5;
        {
            int y;
            y = r0 + 0; d0 = (ox && (unsigned)y < (unsigned)H1) ? src[y*H1 + xx] : 0.f;
            y = r0 + 1; d1 = (ox && (unsigned)y < (unsigned)H1) ? src[y*H1 + xx] : 0.f;
            y = r0 + 2; d2 = (ox && (unsigned)y < (unsigned)H1) ? src[y*H1 + xx] : 0.f;
            y = r0 + 3; d3 = (ox && (unsigned)y < (unsigned)H1) ? src[y*H1 + xx] : 0.f;
            y = r0 + 4; d4 = (ox && (unsigned)y < (unsigned)H1) ? src[y*H1 + xx] : 0.f;
            y = r0 + 5; d5 = (ox && (unsigned)y < (unsigned)H1) ? src[y*H1 + xx] : 0.f;
        }
        t[0][c] = 4.f*d0 - 5.f*d2 + d4;
        t[1][c] = -4.f*d1 - 4.f*d2 + d3 + d4;
        t[2][c] = 4.f*d1 - 4.f*d2 - d3 + d4;
        t[3][c] = -2.f*d1 - d2 + 2.f*d3 + d4;
        t[4][c] = 2.f*d1 - d2 - 2.f*d3 + d4;
        t[5][c] = 4.f*d1 - 5.f*d3 + d5;
    }
    #pragma unroll
    for (int r = 0; r < 6; r++) {
        float t0 = t[r][0], t1 = t[r][1], t2 = t[r][2], t3 = t[r][3], t4 = t[r][4], t5 = t[r][5];
        float v0 = 4.f*t0 - 5.f*t2 + t4;
        float v1 = -4.f*t1 - 4.f*t2 + t3 + t4;
        float v2 = 4.f*t1 - 4.f*t2 - t3 + t4;
        float v3 = -2.f*t1 - t2 + 2.f*t3 + t4;
        float v4 = 2.f*t1 - t2 - 2.f*t3 + t4;
        float v5 = 4.f*t1 - 5.f*t3 + t5;
        V[((size_t)(r*6+0)*CIN + ci)*NT4 + tile] = v0;
        V[((size_t)(r*6+1)*CIN + ci)*NT4 + tile] = v1;
        V[((size_t)(r*6+2)*CIN + ci)*NT4 + tile] = v2;
        V[((size_t)(r*6+3)*CIN + ci)*NT4 + tile] = v3;
        V[((size_t)(r*6+4)*CIN + ci)*NT4 + tile] = v4;
        V[((size_t)(r*6+5)*CIN + ci)*NT4 + tile] = v5;
    }
}

// ---------------- winograd GEMM: M[t][o][tile] = sum_ci U[t][ci][o] * V[t][ci][tile] ----------------
// CTA: 32 o x 256 tiles, 128 threads (po=tid/32: 8 o as 4 pairs; tx: 8 tiles stride 32).
#define GKC 8
template<int CIN>
__global__ __launch_bounds__(128, 4)
void k_gemm(const float* __restrict__ U, const float* __restrict__ V, float* __restrict__ M)
{
    __shared__ __align__(16) float sV[2][GKC*256];   // 16 KB
    __shared__ __align__(16) float sU[2][GKC*32];    // 2 KB

    int tid = threadIdx.x;
    int po  = tid >> 5;
    int tx  = tid & 31;
    int tile0 = blockIdx.x * 256;
    int o0    = blockIdx.y * 32;
    int tap   = blockIdx.z;

    const float* Vt = V + (size_t)tap*CIN*NT4;
    const float* Ut = U + (size_t)tap*CIN*C2;
    uint32_t sV_a = smem_u32(&sV[0][0]);
    uint32_t sU_a = smem_u32(&sU[0][0]);

    auto fill = [&](int k, int buf) {
        int ci0 = k*GKC;
        for (int i = tid; i < GKC*64; i += 128) {
            int ci = i >> 6, v = i & 63;
            cp16(sV_a + (uint32_t)(buf*(GKC*256) + ci*256 + v*4)*4u,
                 Vt + (size_t)(ci0+ci)*NT4 + tile0 + v*4);
        }
        if (tid < 64) {
            int ci = tid >> 3, v = tid & 7;
            cp16(sU_a + (uint32_t)(buf*(GKC*32) + ci*32 + v*4)*4u,
                 Ut + (size_t)(ci0+ci)*C2 + o0 + v*4);
        }
        CP_COMMIT();
    };

    ull acc2[4][8];
    #pragma unroll
    for (int q = 0; q < 4; q++)
        #pragma unroll
        for (int j = 0; j < 8; j++) acc2[q][j] = 0ULL;

    fill(0, 0);

    const int NCHUNK = CIN / GKC;
    for (int k = 0; k < NCHUNK; k++) {
        int buf = k & 1;
        asm volatile("cp.async.wait_group 0;" ::: "memory");
        __syncthreads();
        if (k + 1 < NCHUNK) fill(k + 1, buf ^ 1);

        const float* bV = &sV[buf][0];
        const float* bU = &sU[buf][0];
        #pragma unroll
        for (int ci = 0; ci < GKC; ci++) {
            ull vb[8];
            #pragma unroll
            for (int j = 0; j < 8; j++) vb[j] = bcast2(bV[ci*256 + tx + 32*j]);
            ull wp[4];
            #pragma unroll
            for (int q = 0; q < 4; q++)
                wp[q] = *reinterpret_cast<const ull*>(&bU[ci*32 + po*8 + q*2]);
            #pragma unroll
            for (int q = 0; q < 4; q++)
                #pragma unroll
                for (int j = 0; j < 8; j++)
                    ffma2(acc2[q][j], wp[q], vb[j]);
        }
    }

    float* Mt = M + (size_t)tap*C2*NT4;
    #pragma unroll
    for (int q = 0; q < 4; q++) {
        int o = o0 + po*8 + q*2;
        #pragma unroll
        for (int j = 0; j < 8; j++) {
            float a0, a1; unpack2(acc2[q][j], a0, a1);
            Mt[(size_t)o*NT4     + tile0 + tx + 32*j] = a0;
            Mt[(size_t)(o+1)*NT4 + tile0 + tx + 32*j] = a1;
        }
    }
}

// ---------------- F(4,3) inverse transform + epilogue ----------------
template<bool MULS2>
__global__ void k_inv4(const float* __restrict__ emod, const float* __restrict__ smod2,
                       const float* __restrict__ noise, const float* __restrict__ nw,
                       float* __restrict__ out)
{
    int idx = blockIdx.x*256 + threadIdx.x;    // o*NT4 + tile
    if (idx >= C2*NT4) return;
    int txt = idx & 31, ty = (idx >> 5) & 31, b = (idx >> 10) & 7, o = idx >> 13;
    int tile = idx & (NT4-1);

    // s = A^T M  (4x6), reading M column-wise
    float s[4][6];
    #pragma unroll
    for (int c = 0; c < 6; c++) {
        float m0 = g_M[((size_t)(0*6+c)*C2 + o)*NT4 + tile];
        float m1 = g_M[((size_t)(1*6+c)*C2 + o)*NT4 + tile];
        float m2 = g_M[((size_t)(2*6+c)*C2 + o)*NT4 + tile];
        float m3 = g_M[((size_t)(3*6+c)*C2 + o)*NT4 + tile];
        float m4 = g_M[((size_t)(4*6+c)*C2 + o)*NT4 + tile];
        float m5 = g_M[((size_t)(5*6+c)*C2 + o)*NT4 + tile];
        s[0][c] = m0 + m1 + m2 + m3 + m4;
        s[1][c] = m1 - m2 + 2.f*m3 - 2.f*m4;
        s[2][c] = m1 + m2 + 4.f*m3 + 4.f*m4;
        s[3][c] = m1 - m2 + 8.f*m3 - 8.f*m4 + m5;
    }

    int Y0 = 4*ty, X0 = 4*txt;
    float e = emod[b*C2 + o];
    float nwv = nw[0];
    float s2v = MULS2 ? smod2[b*C2 + o] : 1.f;
    const float* nz = noise + ((size_t)b << 14);
    float* dst = out + ((size_t)(b*C2 + o) << 14);

    #pragma unroll
    for (int r = 0; r < 4; r++) {
        float t0 = s[r][0], t1 = s[r][1], t2 = s[r][2], t3 = s[r][3], t4 = s[r][4], t5 = s[r][5];
        float y0 = t0 + t1 + t2 + t3 + t4;
        float y1 = t1 - t2 + 2.f*t3 - 2.f*t4;
        float y2 = t1 + t2 + 4.f*t3 + 4.f*t4;
        float y3 = t1 - t2 + 8.f*t3 - 8.f*t4 + t5;
        int row = (Y0 + r)*H1 + X0;
        float v0 = y0*e + nwv*nz[row];     v0 = (v0>0.f)?v0:0.2f*v0; v0 *= s2v;
        float v1 = y1*e + nwv*nz[row+1];   v1 = (v1>0.f)?v1:0.2f*v1; v1 *= s2v;
        float v2 = y2*e + nwv*nz[row+2];   v2 = (v2>0.f)?v2:0.2f*v2; v2 *= s2v;
        float v3 = y3*e + nwv*nz[row+3];   v3 = (v3>0.f)?v3:0.2f*v3; v3 *= s2v;
        *reinterpret_cast<float4*>(&dst[row]) = make_float4(v0, v1, v2, v3);
    }
}

// ---------------- to_rgb 1x1 (no demod) + upsampled skip ----------------
__global__ void k_rgb(const float* __restrict__ h, const float* __restrict__ rgbw,
                      const float* __restrict__ skip, float* __restrict__ outrgb)
{
    int b = blockIdx.y;
    __shared__ float sw[3][C2];
    for (int i = threadIdx.x; i < 3*C2; i += blockDim.x) {
        int c = i / C2, o = i % C2;
        sw[c][o] = rgbw[c*C2 + o] * g_s3[b*C2 + o] * 0.0625f;  // 1/sqrt(256)
    }
    __syncthreads();
    int p = blockIdx.x*blockDim.x + threadIdx.x;
    float a0 = 0.f, a1 = 0.f, a2 = 0.f;
    for (int o = 0; o < C2; o++) {
        float v = h[(size_t)(b*C2 + o)*NPIX + p];
        a0 += sw[0][o]*v; a1 += sw[1][o]*v; a2 += sw[2][o]*v;
    }
    int X = p % H1, Y = p / H1;
    float sy = Y*0.5f - 0.25f, sx = X*0.5f - 0.25f;
    int y0 = (int)floorf(sy), x0 = (int)floorf(sx);
    float fy = sy - (float)y0, fx = sx - (float)x0;
    int y0c = max(y0, 0), y1c = min(y0+1, H0-1);
    int x0c = max(x0, 0), x1c = min(x0+1, H0-1);
    float a[3] = {a0, a1, a2};
    #pragma unroll
    for (int c = 0; c < 3; c++) {
        const float* sp = skip + (size_t)(b*3 + c)*NPIX0;
        float bv = (1.f-fy)*((1.f-fx)*sp[y0c*H0+x0c] + fx*sp[y0c*H0+x1c])
                 +      fy *((1.f-fx)*sp[y1c*H0+x0c] + fx*sp[y1c*H0+x1c]);
        outrgb[(size_t)(b*3 + c)*NPIX + p] = a[c] + bv;
    }
}

// ---------------- launch ----------------
extern "C" void kernel_launch(void* const* d_in, const int* in_sizes, int n_in,
                              void* d_out, int out_size)
{
    const float* x       = (const float*)d_in[0];
    const float* w1      = (const float*)d_in[1];
    const float* w2      = (const float*)d_in[2];
    const float* skip    = (const float*)d_in[3];
    const float* noise1  = (const float*)d_in[4];
    const float* noise2  = (const float*)d_in[5];
    const float* conv1_w = (const float*)d_in[6];
    const float* mod1_w  = (const float*)d_in[7];
    const float* mod1_b  = (const float*)d_in[8];
    const float* conv2_w = (const float*)d_in[9];
    const float* mod2_w  = (const float*)d_in[10];
    const float* mod2_b  = (const float*)d_in[11];
    const float* rgb_w   = (const float*)d_in[12];
    const float* mod3_w  = (const float*)d_in[13];
    const float* mod3_b  = (const float*)d_in[14];
    const float* nw1     = (const float*)d_in[15];
    const float* nw2     = (const float*)d_in[16];
    float* out = (float*)d_out;

    void *p_up, *p_h1, *p_e1, *p_e2, *p_s2, *p_U1, *p_U2, *p_V, *p_M;
    cudaGetSymbolAddress(&p_up, g_up);
    cudaGetSymbolAddress(&p_h1, g_h1);
    cudaGetSymbolAddress(&p_e1, g_e1);
    cudaGetSymbolAddress(&p_e2, g_e2);
    cudaGetSymbolAddress(&p_s2, g_s2);
    cudaGetSymbolAddress(&p_U1, g_U1);
    cudaGetSymbolAddress(&p_U2, g_U2);
    cudaGetSymbolAddress(&p_V,  g_V);
    cudaGetSymbolAddress(&p_M,  g_M);

    float* out_h   = out;                                // [8,256,128,128]
    float* out_rgb = out + (size_t)BB*C2*NPIX;           // [8,3,128,128]

    // 1. styles + demod scalars
    {
        int n = BB*C1 + 2*BB*C2;
        k_styles<<<(n + 255)/256, 256>>>(w1, w2, mod1_w, mod1_b, mod2_w, mod2_b, mod3_w, mod3_b);
    }
    {
        int n = C2*C1 + C2*C2;
        k_wsq<<<(n + 255)/256, 256>>>(conv1_w, conv2_w);
    }
    k_demod<<<(2*BB*C2 + 255)/256, 256>>>();
    // 2. F(4,3) weight transforms
    k_wt4<<<(C1*C2 + 255)/256, 256>>>(conv1_w, (float*)p_U1, C1);
    k_wt4<<<(C2*C2 + 255)/256, 256>>>(conv2_w, (float*)p_U2, C2);
    // 3. upsample + modulate(s1)
    {
        size_t n = (size_t)BB*C1*NPIX/2;
        k_upmod<<<(unsigned)((n + 255)/256), 256>>>(x);
    }
    // 4. conv1 via winograd F(4x4,3x3)
    k_itrans4<<<(C1*NT4)/256, 256>>>((const float*)p_up, (float*)p_V, C1);
    k_gemm<C1><<<dim3(NT4/256, C2/32, 36), 128>>>((const float*)p_U1, (const float*)p_V, (float*)p_M);
    k_inv4<true><<<(C2*NT4)/256, 256>>>((const float*)p_e1, (const float*)p_s2, noise1, nw1, (float*)p_h1);
    // 5. conv2 via winograd F(4x4,3x3) (reuse V, M)
    k_itrans4<<<(C2*NT4)/256, 256>>>((const float*)p_h1, (float*)p_V, C2);
    k_gemm<C2><<<dim3(NT4/256, C2/32, 36), 128>>>((const float*)p_U2, (const float*)p_V, (float*)p_M);
    k_inv4<false><<<(C2*NT4)/256, 256>>>((const float*)p_e2, nullptr, noise2, nw2, out_h);
    // 6. to_rgb + upsampled skip
    k_rgb<<<dim3(NPIX/256, BB), 256>>>(out_h, rgb_w, skip, out_rgb);
}